// round 5
// baseline (speedup 1.0000x reference)
#include <cuda_runtime.h>

#define HID 2048
#define SEQ 2048
#define BATCH 2
#define NH 16
#define HD 128
#define MTOT (BATCH*SEQ)   /* 4096 */

// ---------------- scratch (no allocations allowed) ----------------
__device__ float g_Q[MTOT * HID];   // 33.5 MB
__device__ float g_K[MTOT * HD];    // 2 MB
__device__ float g_V[MTOT * HD];    // 2 MB
__device__ float g_A[MTOT * HID];   // 33.5 MB attn output (pre O-proj)

// ---------------- packed f32x2 helpers (FFMA2 path, 2x fp32 rate) ----------------
typedef unsigned long long u64;

__device__ __forceinline__ void fma2(u64 &d, u64 a, u64 b) {
    asm("fma.rn.f32x2 %0, %1, %2, %0;" : "+l"(d) : "l"(a), "l"(b));
}
__device__ __forceinline__ u64 splat2(float x) {
    u64 r; asm("mov.b64 %0, {%1, %1};" : "=l"(r) : "f"(x)); return r;
}
__device__ __forceinline__ u64 mul2(u64 a, u64 b) {
    u64 r; asm("mul.rn.f32x2 %0, %1, %2;" : "=l"(r) : "l"(a), "l"(b)); return r;
}
__device__ __forceinline__ float2 unpack2(u64 v) {
    float2 f; asm("mov.b64 {%0, %1}, %2;" : "=f"(f.x), "=f"(f.y) : "l"(v)); return f;
}

// ---------------- generic tiled SGEMM with bias, f32x2 inner loop ----------------
// C[M,N] = A[M,K] @ B[K,N] + bias[N], all row-major. 256 threads.
// Thread (ty, tx) = (tid>>4, tid&15) computes TM rows x (2*TNP) cols.
// Columns per thread: col = tx*2 + j*32 (j < TNP)  -> conflict-free 8B LDS.
template<int BM, int BN, int TM, int TNP>
__global__ __launch_bounds__(256) void sgemm_bias(
    const float* __restrict__ A, const float* __restrict__ B,
    const float* __restrict__ bias, float* __restrict__ C,
    int M, int N, int K)
{
    constexpr int BKK = 16;
    __shared__ __align__(16) float As[BKK][BM + 4];  // transposed: As[k][m]
    __shared__ __align__(16) float Bs[BKK][BN + 4];

    const int tid = threadIdx.x;
    const int tx = tid & 15;
    const int ty = tid >> 4;
    const int row0 = blockIdx.y * BM;
    const int col0 = blockIdx.x * BN;

    u64 c2[TM][TNP];
    #pragma unroll
    for (int i = 0; i < TM; i++)
        #pragma unroll
        for (int j = 0; j < TNP; j++) c2[i][j] = 0ull;

    const float* Ab = A + (size_t)row0 * K;
    const float* Bb = B + col0;

    for (int k0 = 0; k0 < K; k0 += BKK) {
        // load A tile (BM x 16), store transposed
        for (int t = tid; t < BM * 4; t += 256) {
            int r = t >> 2;
            int c = (t & 3) * 4;
            float4 v = *(const float4*)(Ab + (size_t)r * K + k0 + c);
            As[c + 0][r] = v.x; As[c + 1][r] = v.y;
            As[c + 2][r] = v.z; As[c + 3][r] = v.w;
        }
        // load B tile (16 x BN)
        for (int t = tid; t < BN * 4; t += 256) {
            int r = t / (BN / 4);
            int c = (t % (BN / 4)) * 4;
            *(float4*)&Bs[r][c] = *(const float4*)(Bb + (size_t)(k0 + r) * N + c);
        }
        __syncthreads();

        #pragma unroll
        for (int kk = 0; kk < BKK; kk++) {
            u64 b2[TNP];
            #pragma unroll
            for (int j = 0; j < TNP; j++)
                b2[j] = *(const u64*)&Bs[kk][tx * 2 + j * 32];
            #pragma unroll
            for (int i = 0; i < TM; i++) {
                u64 a2 = splat2(As[kk][ty * TM + i]);
                #pragma unroll
                for (int j = 0; j < TNP; j++) fma2(c2[i][j], a2, b2[j]);
            }
        }
        __syncthreads();
    }

    #pragma unroll
    for (int i = 0; i < TM; i++) {
        int row = row0 + ty * TM + i;
        #pragma unroll
        for (int j = 0; j < TNP; j++) {
            int col = col0 + tx * 2 + j * 32;
            float2 v = unpack2(c2[i][j]);
            v.x += bias[col];
            v.y += bias[col + 1];
            *(float2*)(C + (size_t)row * N + col) = v;
        }
    }
}

// ---------------- flash attention (fp32, f32x2 inner loops) ----------------
// Block: one (batch, head, 32-q-row tile). 256 threads = 32 q-rows x 8 lanes.
// Streams K/V in 64-row tiles through shared memory; online softmax.
#define BQ 32
#define BKT 64
#define QSTR 132          /* padded row stride (floats) for q/k/v tiles */
#define PSTR 68           /* padded row stride for probability tile */

__global__ __launch_bounds__(256) void attn_kernel(
    const float* __restrict__ Q, const float* __restrict__ Kp,
    const float* __restrict__ Vp, float* __restrict__ Out)
{
    extern __shared__ __align__(16) float sm[];
    float* q_sh = sm;                                 // BQ  * QSTR
    float* k_sh = q_sh + BQ * QSTR;                   // BKT * QSTR
    float* v_sh = k_sh + BKT * QSTR;                  // BKT * QSTR
    float* p_sh = v_sh + BKT * QSTR;                  // BQ  * PSTR

    const int tid  = threadIdx.x;
    const int qr   = tid >> 3;      // 0..31 : q row within tile
    const int lane = tid & 7;       // 0..7  : 8 lanes cooperate on a row
    const int qt = blockIdx.x;
    const int h  = blockIdx.y;
    const int b  = blockIdx.z;
    const float scale = 0.08838834764831845f;  // 1/sqrt(128)

    // load Q tile (scale folded in)
    const size_t qbase = ((size_t)(b * SEQ + qt * BQ)) * HID + h * HD;
    for (int t = tid; t < BQ * (HD / 4); t += 256) {
        int r = t >> 5;             // 32 float4 per row
        int c = (t & 31) * 4;
        float4 v = *(const float4*)(Q + qbase + (size_t)r * HID + c);
        v.x *= scale; v.y *= scale; v.z *= scale; v.w *= scale;
        *(float4*)&q_sh[r * QSTR + c] = v;
    }

    float m = -1e30f, l = 0.f;
    u64 o2[8];                      // 16 output dims: d = lane*2 + 16*p + {0,1}
    #pragma unroll
    for (int p = 0; p < 8; p++) o2[p] = 0ull;

    const size_t kvbase = (size_t)b * SEQ * HD;

    for (int kt = 0; kt < SEQ / BKT; kt++) {
        __syncthreads();   // previous tile fully consumed
        const float* Ksrc = Kp + kvbase + (size_t)kt * BKT * HD;
        const float* Vsrc = Vp + kvbase + (size_t)kt * BKT * HD;
        for (int t = tid; t < BKT * (HD / 4); t += 256) {
            int r = t >> 5;
            int c = (t & 31) * 4;
            *(float4*)&k_sh[r * QSTR + c] = *(const float4*)(Ksrc + (size_t)r * HD + c);
            *(float4*)&v_sh[r * QSTR + c] = *(const float4*)(Vsrc + (size_t)r * HD + c);
        }
        __syncthreads();

        // ---- scores: thread owns k-cols j = lane + 8*i, i<8 ----
        u64 acc[8];
        #pragma unroll
        for (int i = 0; i < 8; i++) acc[i] = 0ull;
        const ulonglong2* qrow = (const ulonglong2*)(q_sh + qr * QSTR);
        #pragma unroll 4
        for (int d4 = 0; d4 < HD / 4; d4++) {
            ulonglong2 q2 = qrow[d4];
            #pragma unroll
            for (int i = 0; i < 8; i++) {
                const ulonglong2* krow =
                    (const ulonglong2*)(k_sh + (lane + 8 * i) * QSTR);
                ulonglong2 k2 = krow[d4];
                fma2(acc[i], q2.x, k2.x);
                fma2(acc[i], q2.y, k2.y);
            }
        }
        float s[8];
        float tmax = -1e30f;
        #pragma unroll
        for (int i = 0; i < 8; i++) {
            float2 f = unpack2(acc[i]);
            s[i] = f.x + f.y;
            tmax = fmaxf(tmax, s[i]);
        }
        // max over the 8 lanes of this row (lanes are an aligned group of 8)
        tmax = fmaxf(tmax, __shfl_xor_sync(0xffffffffu, tmax, 1));
        tmax = fmaxf(tmax, __shfl_xor_sync(0xffffffffu, tmax, 2));
        tmax = fmaxf(tmax, __shfl_xor_sync(0xffffffffu, tmax, 4));

        float mnew = fmaxf(m, tmax);
        float fct  = __expf(m - mnew);
        m = mnew;
        l *= fct;
        u64 f2 = splat2(fct);
        #pragma unroll
        for (int p = 0; p < 8; p++) o2[p] = mul2(o2[p], f2);

        float psum = 0.f;
        #pragma unroll
        for (int i = 0; i < 8; i++) {
            float pv = __expf(s[i] - m);
            psum += pv;
            p_sh[qr * PSTR + lane + 8 * i] = pv;
        }
        psum += __shfl_xor_sync(0xffffffffu, psum, 1);
        psum += __shfl_xor_sync(0xffffffffu, psum, 2);
        psum += __shfl_xor_sync(0xffffffffu, psum, 4);
        l += psum;
        __syncwarp();   // p_sh row written by this warp, read by this warp

        // ---- P @ V ----
        #pragma unroll 4
        for (int j4 = 0; j4 < BKT / 4; j4++) {
            float4 p4 = *(const float4*)&p_sh[qr * PSTR + j4 * 4];
            float pj[4] = {p4.x, p4.y, p4.z, p4.w};
            #pragma unroll
            for (int jj = 0; jj < 4; jj++) {
                u64 pj2 = splat2(pj[jj]);
                const u64* vrow = (const u64*)(v_sh + (j4 * 4 + jj) * QSTR);
                #pragma unroll
                for (int p = 0; p < 8; p++) fma2(o2[p], pj2, vrow[lane + 8 * p]);
            }
        }
    }

    float inv = 1.f / l;
    float* outp = Out + ((size_t)(b * SEQ + qt * BQ + qr)) * HID + h * HD + lane * 2;
    #pragma unroll
    for (int p = 0; p < 8; p++) {
        float2 v = unpack2(o2[p]);
        v.x *= inv; v.y *= inv;
        *(float2*)(outp + 16 * p) = v;
    }
}

static const int ATTN_SMEM =
    (BQ * QSTR + 2 * BKT * QSTR + BQ * PSTR) * (int)sizeof(float);  // 93184 B

// ---------------- launch ----------------
extern "C" void kernel_launch(void* const* d_in, const int* in_sizes, int n_in,
                              void* d_out, int out_size)
{
    const float* hidden = (const float*)d_in[0];
    const float* Wq = (const float*)d_in[1];
    const float* bq = (const float*)d_in[2];
    const float* Wk = (const float*)d_in[3];
    const float* bk = (const float*)d_in[4];
    const float* Wv = (const float*)d_in[5];
    const float* bv = (const float*)d_in[6];
    const float* Wo = (const float*)d_in[7];
    const float* bo = (const float*)d_in[8];
    float* out = (float*)d_out;

    float *Qb, *Kb, *Vb, *Ab;
    cudaGetSymbolAddress((void**)&Qb, g_Q);
    cudaGetSymbolAddress((void**)&Kb, g_K);
    cudaGetSymbolAddress((void**)&Vb, g_V);
    cudaGetSymbolAddress((void**)&Ab, g_A);

    // K / V projections: [4096,2048] @ [2048,128]  (small tiles for parallelism)
    {
        dim3 grid(HD / 64, MTOT / 64);
        sgemm_bias<64, 64, 4, 2><<<grid, 256>>>(hidden, Wk, bk, Kb, MTOT, HD, HID);
        sgemm_bias<64, 64, 4, 2><<<grid, 256>>>(hidden, Wv, bv, Vb, MTOT, HD, HID);
    }
    // Q projection: [4096,2048] @ [2048,2048]
    {
        dim3 grid(HID / 128, MTOT / 128);
        sgemm_bias<128, 128, 8, 4><<<grid, 256>>>(hidden, Wq, bq, Qb, MTOT, HID, HID);
    }
    // attention
    {
        cudaFuncSetAttribute(attn_kernel,
                             cudaFuncAttributeMaxDynamicSharedMemorySize, ATTN_SMEM);
        dim3 grid(SEQ / BQ, NH, BATCH);
        attn_kernel<<<grid, 256, ATTN_SMEM>>>(Qb, Kb, Vb, Ab);
    }
    // O projection: [4096,2048] @ [2048,2048] -> d_out
    {
        dim3 grid(HID / 128, MTOT / 128);
        sgemm_bias<128, 128, 8, 4><<<grid, 256>>>(Ab, Wo, bo, out, MTOT, HID, HID);
    }
}

// round 8
// speedup vs baseline: 2.9084x; 2.9084x over previous
#include <cuda_runtime.h>
#include <cstdint>

#define HID 2048
#define SEQ 2048
#define BATCH 2
#define NH 16
#define HD 128
#define MTOT (BATCH*SEQ)   /* 4096 */

// ---------------- scratch (no allocations allowed) ----------------
__device__ float g_Q[MTOT * HID];   // 33.5 MB
__device__ float g_K[MTOT * HD];    // 2 MB
__device__ float g_V[MTOT * HD];    // 2 MB
__device__ float g_A[MTOT * HID];   // 33.5 MB attn output (pre O-proj)

// ---------------- tf32 helpers ----------------
__device__ __forceinline__ uint32_t f2tf(float x) {
    uint32_t r; asm("cvt.rna.tf32.f32 %0, %1;" : "=r"(r) : "f"(x)); return r;
}
__device__ __forceinline__ void split_tf(float x, uint32_t &hi, uint32_t &lo) {
    hi = f2tf(x);
    lo = f2tf(x - __uint_as_float(hi));
}
// D += A(16x8) * B(8x8), tf32, fp32 accum
__device__ __forceinline__ void mma8(float* d, const uint32_t* a, uint32_t b0, uint32_t b1) {
    asm volatile(
        "mma.sync.aligned.m16n8k8.row.col.f32.tf32.tf32.f32 "
        "{%0,%1,%2,%3}, {%4,%5,%6,%7}, {%8,%9}, {%0,%1,%2,%3};"
        : "+f"(d[0]), "+f"(d[1]), "+f"(d[2]), "+f"(d[3])
        : "r"(a[0]), "r"(a[1]), "r"(a[2]), "r"(a[3]), "r"(b0), "r"(b1));
}

// ======================================================================
// 3xTF32 GEMM: C[M,N] = A[M,K] @ B[K,N] + bias, row-major, fp32-accurate.
// 256 thr / 8 warps, block tile 128x128, BK=32. Warp tile 32x64.
// gridDim.z==2 selects (B0,bias0,C0) vs (B1,bias1,C1)  (fused K/V proj).
// ======================================================================
#define SA 36    /* A smem stride: 36%32=4 -> frag bank 4g+t, bijective */
#define SB 136   /* B smem stride: 136%32=8 -> frag bank 8t+g, bijective */
#define GEMM_SMEM ((2*128*SA + 2*32*SB) * 4)   /* 71680 B */

__global__ __launch_bounds__(256) void gemm3x(
    const float* __restrict__ A,
    const float* __restrict__ B0, const float* __restrict__ bias0, float* __restrict__ C0,
    const float* __restrict__ B1, const float* __restrict__ bias1, float* __restrict__ C1,
    int N, int K)
{
    extern __shared__ uint32_t smg[];
    uint32_t* Ah = smg;                  // 128*SA
    uint32_t* Al = Ah + 128*SA;
    uint32_t* Bh = Al + 128*SA;          // 32*SB
    uint32_t* Bl = Bh + 32*SB;

    const float* B    = blockIdx.z ? B1    : B0;
    const float* bias = blockIdx.z ? bias1 : bias0;
    float*       C    = blockIdx.z ? C1    : C0;

    const int tid  = threadIdx.x;
    const int lane = tid & 31, warp = tid >> 5;
    const int g = lane >> 2, t = lane & 3;
    const int wm = (warp >> 1) * 32;
    const int wn = (warp & 1) * 64;
    const int row0 = blockIdx.y * 128;
    const int col0 = blockIdx.x * 128;

    float acc[2][8][4];
    #pragma unroll
    for (int i = 0; i < 2; i++)
        #pragma unroll
        for (int j = 0; j < 8; j++)
            #pragma unroll
            for (int c = 0; c < 4; c++) acc[i][j][c] = 0.f;

    for (int k0 = 0; k0 < K; k0 += 32) {
        // A tile 128x32 -> hi/lo  (1024 float4)
        #pragma unroll
        for (int j = 0; j < 4; j++) {
            int idx = tid + j * 256;
            int r = idx >> 3, c = (idx & 7) * 4;
            float4 v = *(const float4*)(A + (size_t)(row0 + r) * K + k0 + c);
            uint32_t* ph = Ah + r * SA + c;
            uint32_t* pl = Al + r * SA + c;
            split_tf(v.x, ph[0], pl[0]); split_tf(v.y, ph[1], pl[1]);
            split_tf(v.z, ph[2], pl[2]); split_tf(v.w, ph[3], pl[3]);
        }
        // B tile 32x128 -> hi/lo  (1024 float4)
        #pragma unroll
        for (int j = 0; j < 4; j++) {
            int idx = tid + j * 256;
            int r = idx >> 5, c = (idx & 31) * 4;
            float4 v = *(const float4*)(B + (size_t)(k0 + r) * N + col0 + c);
            uint32_t* ph = Bh + r * SB + c;
            uint32_t* pl = Bl + r * SB + c;
            split_tf(v.x, ph[0], pl[0]); split_tf(v.y, ph[1], pl[1]);
            split_tf(v.z, ph[2], pl[2]); split_tf(v.w, ph[3], pl[3]);
        }
        __syncthreads();

        #pragma unroll
        for (int s = 0; s < 4; s++) {
            const int kb = s * 8;
            uint32_t ah[2][4], al[2][4];
            #pragma unroll
            for (int mt = 0; mt < 2; mt++) {
                int rm = wm + mt * 16 + g;
                ah[mt][0] = Ah[rm * SA + kb + t];
                ah[mt][1] = Ah[(rm + 8) * SA + kb + t];
                ah[mt][2] = Ah[rm * SA + kb + t + 4];
                ah[mt][3] = Ah[(rm + 8) * SA + kb + t + 4];
                al[mt][0] = Al[rm * SA + kb + t];
                al[mt][1] = Al[(rm + 8) * SA + kb + t];
                al[mt][2] = Al[rm * SA + kb + t + 4];
                al[mt][3] = Al[(rm + 8) * SA + kb + t + 4];
            }
            #pragma unroll
            for (int nt = 0; nt < 8; nt++) {
                int cn = wn + nt * 8 + g;
                uint32_t bh0 = Bh[(kb + t) * SB + cn];
                uint32_t bh1 = Bh[(kb + t + 4) * SB + cn];
                uint32_t bl0 = Bl[(kb + t) * SB + cn];
                uint32_t bl1 = Bl[(kb + t + 4) * SB + cn];
                #pragma unroll
                for (int mt = 0; mt < 2; mt++) {
                    mma8(acc[mt][nt], ah[mt], bh0, bh1);   // hi*hi
                    mma8(acc[mt][nt], al[mt], bh0, bh1);   // lo*hi
                    mma8(acc[mt][nt], ah[mt], bl0, bl1);   // hi*lo
                }
            }
        }
        __syncthreads();
    }

    #pragma unroll
    for (int mt = 0; mt < 2; mt++) {
        int row = row0 + wm + mt * 16 + g;
        #pragma unroll
        for (int nt = 0; nt < 8; nt++) {
            int col = col0 + wn + nt * 8 + 2 * t;
            float bx = bias[col], by = bias[col + 1];
            float2 v0 = { acc[mt][nt][0] + bx, acc[mt][nt][1] + by };
            float2 v1 = { acc[mt][nt][2] + bx, acc[mt][nt][3] + by };
            *(float2*)(C + (size_t)row * N + col)       = v0;
            *(float2*)(C + (size_t)(row + 8) * N + col) = v1;
        }
    }
}

// ======================================================================
// Flash attention, tf32 mma. Block = (b, h, 128-q-row tile), 256 thr.
// Warp w owns q rows [w*16, w*16+16): QK^T, softmax, P·V all warp-local.
// K/V streamed in 64-row tiles.
// ======================================================================
#define SQm 132   /* 132%32=4 -> A-frag bank 4g+t  */
#define SKm 132   /* B-frag (QK): bank 4g+t        */
#define SVm 136   /* B-frag (PV): bank 8t+g        */
#define SPm 68    /* 68%32=4 -> A-frag bank 4g+t   */
#define ATTN_SMEM ((128*SQm + 64*SKm + 64*SVm + 128*SPm) * 4)   /* 171008 B */

__global__ __launch_bounds__(256) void attn_tf32(
    const float* __restrict__ Q, const float* __restrict__ Kp,
    const float* __restrict__ Vp, float* __restrict__ Out)
{
    extern __shared__ uint32_t sm[];
    uint32_t* Qs = sm;                    // 128 x SQm
    uint32_t* Ks = Qs + 128 * SQm;        // 64  x SKm
    uint32_t* Vs = Ks + 64 * SKm;         // 64  x SVm
    uint32_t* Ps = Vs + 64 * SVm;         // 128 x SPm

    const int tid  = threadIdx.x;
    const int lane = tid & 31, warp = tid >> 5;
    const int g = lane >> 2, t = lane & 3;
    const int qt = blockIdx.x, h = blockIdx.y, b = blockIdx.z;
    const float scale = 0.08838834764831845f;   // 1/sqrt(128)

    // load Q tile (scale folded, tf32): 4096 float4
    const size_t qbase = ((size_t)(b * SEQ + qt * 128)) * HID + h * HD;
    #pragma unroll
    for (int j = 0; j < 16; j++) {
        int idx = tid + j * 256;
        int r = idx >> 5, c = (idx & 31) * 4;
        float4 v = *(const float4*)(Q + qbase + (size_t)r * HID + c);
        uint32_t* p = Qs + r * SQm + c;
        p[0] = f2tf(v.x * scale); p[1] = f2tf(v.y * scale);
        p[2] = f2tf(v.z * scale); p[3] = f2tf(v.w * scale);
    }

    float mrow[2] = { -1e30f, -1e30f };
    float lrow[2] = { 0.f, 0.f };
    float o[16][4];
    #pragma unroll
    for (int nt = 0; nt < 16; nt++)
        #pragma unroll
        for (int c = 0; c < 4; c++) o[nt][c] = 0.f;

    const size_t kvb = (size_t)b * SEQ * HD;
    const int prow0 = (warp * 16 + g) * SPm;
    const int prow1 = prow0 + 8 * SPm;

    for (int kt = 0; kt < SEQ / 64; kt++) {
        __syncthreads();
        // load K,V 64x128 tiles (tf32): 2048 float4 each
        #pragma unroll
        for (int j = 0; j < 8; j++) {
            int idx = tid + j * 256;
            int r = idx >> 5, c = (idx & 31) * 4;
            const size_t go = kvb + (size_t)(kt * 64 + r) * HD + c;
            float4 kv = *(const float4*)(Kp + go);
            float4 vv = *(const float4*)(Vp + go);
            uint32_t* pk = Ks + r * SKm + c;
            pk[0] = f2tf(kv.x); pk[1] = f2tf(kv.y); pk[2] = f2tf(kv.z); pk[3] = f2tf(kv.w);
            uint32_t* pv = Vs + r * SVm + c;
            pv[0] = f2tf(vv.x); pv[1] = f2tf(vv.y); pv[2] = f2tf(vv.z); pv[3] = f2tf(vv.w);
        }
        __syncthreads();

        // ---- S(16x64) = Q_warp @ K^T ----
        float s[8][4];
        #pragma unroll
        for (int nt = 0; nt < 8; nt++)
            #pragma unroll
            for (int c = 0; c < 4; c++) s[nt][c] = 0.f;

        #pragma unroll
        for (int ks = 0; ks < 16; ks++) {
            const int kb = ks * 8;
            const int rm = warp * 16 + g;
            uint32_t a[4];
            a[0] = Qs[rm * SQm + kb + t];
            a[1] = Qs[(rm + 8) * SQm + kb + t];
            a[2] = Qs[rm * SQm + kb + t + 4];
            a[3] = Qs[(rm + 8) * SQm + kb + t + 4];
            #pragma unroll
            for (int nt = 0; nt < 8; nt++) {
                int cn = nt * 8 + g;
                uint32_t b0 = Ks[cn * SKm + kb + t];
                uint32_t b1 = Ks[cn * SKm + kb + t + 4];
                mma8(s[nt], a, b0, b1);
            }
        }

        // ---- online softmax (rows g, g+8; lanes sharing row: xor 1,2) ----
        float tm0 = -1e30f, tm1 = -1e30f;
        #pragma unroll
        for (int nt = 0; nt < 8; nt++) {
            tm0 = fmaxf(tm0, fmaxf(s[nt][0], s[nt][1]));
            tm1 = fmaxf(tm1, fmaxf(s[nt][2], s[nt][3]));
        }
        tm0 = fmaxf(tm0, __shfl_xor_sync(0xffffffffu, tm0, 1));
        tm0 = fmaxf(tm0, __shfl_xor_sync(0xffffffffu, tm0, 2));
        tm1 = fmaxf(tm1, __shfl_xor_sync(0xffffffffu, tm1, 1));
        tm1 = fmaxf(tm1, __shfl_xor_sync(0xffffffffu, tm1, 2));

        float mn0 = fmaxf(mrow[0], tm0), mn1 = fmaxf(mrow[1], tm1);
        float f0 = __expf(mrow[0] - mn0), f1 = __expf(mrow[1] - mn1);
        mrow[0] = mn0; mrow[1] = mn1;
        lrow[0] *= f0; lrow[1] *= f1;
        #pragma unroll
        for (int nt = 0; nt < 16; nt++) {
            o[nt][0] *= f0; o[nt][1] *= f0;
            o[nt][2] *= f1; o[nt][3] *= f1;
        }

        float ps0 = 0.f, ps1 = 0.f;
        #pragma unroll
        for (int nt = 0; nt < 8; nt++) {
            int col = nt * 8 + 2 * t;
            float p0 = __expf(s[nt][0] - mn0); ps0 += p0;
            float p1 = __expf(s[nt][1] - mn0); ps0 += p1;
            float p2 = __expf(s[nt][2] - mn1); ps1 += p2;
            float p3 = __expf(s[nt][3] - mn1); ps1 += p3;
            Ps[prow0 + col]     = f2tf(p0);
            Ps[prow0 + col + 1] = f2tf(p1);
            Ps[prow1 + col]     = f2tf(p2);
            Ps[prow1 + col + 1] = f2tf(p3);
        }
        ps0 += __shfl_xor_sync(0xffffffffu, ps0, 1);
        ps0 += __shfl_xor_sync(0xffffffffu, ps0, 2);
        ps1 += __shfl_xor_sync(0xffffffffu, ps1, 1);
        ps1 += __shfl_xor_sync(0xffffffffu, ps1, 2);
        lrow[0] += ps0; lrow[1] += ps1;
        __syncwarp();

        // ---- O(16x128) += P(16x64) @ V(64x128) ----
        #pragma unroll
        for (int ks = 0; ks < 8; ks++) {
            const int kb = ks * 8;
            uint32_t a[4];
            a[0] = Ps[prow0 + kb + t];
            a[1] = Ps[prow1 + kb + t];
            a[2] = Ps[prow0 + kb + t + 4];
            a[3] = Ps[prow1 + kb + t + 4];
            #pragma unroll
            for (int nt = 0; nt < 16; nt++) {
                int cn = nt * 8 + g;
                uint32_t b0 = Vs[(kb + t) * SVm + cn];
                uint32_t b1 = Vs[(kb + t + 4) * SVm + cn];
                mma8(o[nt], a, b0, b1);
            }
        }
        __syncwarp();   // Ps reads done before next tile's writes
    }

    // epilogue
    float inv0 = 1.f / lrow[0], inv1 = 1.f / lrow[1];
    const size_t ob = ((size_t)(b * SEQ + qt * 128 + warp * 16 + g)) * HID + h * HD;
    #pragma unroll
    for (int nt = 0; nt < 16; nt++) {
        int col = nt * 8 + 2 * t;
        float2 v0 = { o[nt][0] * inv0, o[nt][1] * inv0 };
        float2 v1 = { o[nt][2] * inv1, o[nt][3] * inv1 };
        *(float2*)(Out + ob + col)            = v0;
        *(float2*)(Out + ob + 8 * HID + col)  = v1;
    }
}

// ---------------- launch ----------------
extern "C" void kernel_launch(void* const* d_in, const int* in_sizes, int n_in,
                              void* d_out, int out_size)
{
    const float* hidden = (const float*)d_in[0];
    const float* Wq = (const float*)d_in[1];
    const float* bq = (const float*)d_in[2];
    const float* Wk = (const float*)d_in[3];
    const float* bk = (const float*)d_in[4];
    const float* Wv = (const float*)d_in[5];
    const float* bv = (const float*)d_in[6];
    const float* Wo = (const float*)d_in[7];
    const float* bo = (const float*)d_in[8];
    float* out = (float*)d_out;

    float *Qb, *Kb, *Vb, *Ab;
    cudaGetSymbolAddress((void**)&Qb, g_Q);
    cudaGetSymbolAddress((void**)&Kb, g_K);
    cudaGetSymbolAddress((void**)&Vb, g_V);
    cudaGetSymbolAddress((void**)&Ab, g_A);

    cudaFuncSetAttribute(gemm3x, cudaFuncAttributeMaxDynamicSharedMemorySize, GEMM_SMEM);
    cudaFuncSetAttribute(attn_tf32, cudaFuncAttributeMaxDynamicSharedMemorySize, ATTN_SMEM);

    // K / V projections fused: grid.z selects weight set. N=128.
    {
        dim3 grid(1, MTOT / 128, 2);
        gemm3x<<<grid, 256, GEMM_SMEM>>>(hidden, Wk, bk, Kb, Wv, bv, Vb, HD, HID);
    }
    // Q projection: [4096,2048] @ [2048,2048]
    {
        dim3 grid(HID / 128, MTOT / 128, 1);
        gemm3x<<<grid, 256, GEMM_SMEM>>>(hidden, Wq, bq, Qb, Wq, bq, Qb, HID, HID);
    }
    // attention
    {
        dim3 grid(SEQ / 128, NH, BATCH);
        attn_tf32<<<grid, 256, ATTN_SMEM>>>(Qb, Kb, Vb, Ab);
    }
    // O projection -> d_out
    {
        dim3 grid(HID / 128, MTOT / 128, 1);
        gemm3x<<<grid, 256, GEMM_SMEM>>>(Ab, Wo, bo, out, Wo, bo, out, HID, HID);
    }
}

// round 9
// speedup vs baseline: 3.1984x; 1.0997x over previous
#include <cuda_runtime.h>
#include <cstdint>

#define HID 2048
#define SEQ 2048
#define BATCH 2
#define NH 16
#define HD 128
#define MTOT (BATCH*SEQ)   /* 4096 */

// ---------------- scratch (no allocations allowed) ----------------
__device__ uint32_t g_Hh[MTOT*HID], g_Hl[MTOT*HID];   // hidden split
__device__ uint32_t g_Wqh[HID*HID], g_Wql[HID*HID];
__device__ uint32_t g_Woh[HID*HID], g_Wol[HID*HID];
__device__ uint32_t g_Wkh[HID*HD],  g_Wkl[HID*HD];
__device__ uint32_t g_Wvh[HID*HD],  g_Wvl[HID*HD];
__device__ uint32_t g_Qt[MTOT*HID];                   // Q tf32, scale folded
__device__ uint32_t g_Kt[MTOT*HD],  g_Vt[MTOT*HD];    // K,V tf32
__device__ uint32_t g_Ah[MTOT*HID], g_Al[MTOT*HID];   // attn out split

// ---------------- tf32 / mma / cp.async helpers ----------------
__device__ __forceinline__ uint32_t f2tf(float x) {
    uint32_t r; asm("cvt.rna.tf32.f32 %0, %1;" : "=r"(r) : "f"(x)); return r;
}
__device__ __forceinline__ void split_tf(float x, uint32_t &hi, uint32_t &lo) {
    hi = f2tf(x);
    lo = f2tf(x - __uint_as_float(hi));
}
__device__ __forceinline__ void mma8(float* d, const uint32_t* a, uint32_t b0, uint32_t b1) {
    asm volatile(
        "mma.sync.aligned.m16n8k8.row.col.f32.tf32.tf32.f32 "
        "{%0,%1,%2,%3}, {%4,%5,%6,%7}, {%8,%9}, {%0,%1,%2,%3};"
        : "+f"(d[0]), "+f"(d[1]), "+f"(d[2]), "+f"(d[3])
        : "r"(a[0]), "r"(a[1]), "r"(a[2]), "r"(a[3]), "r"(b0), "r"(b1));
}
__device__ __forceinline__ uint32_t s2u(const void* p) {
    return (uint32_t)__cvta_generic_to_shared(p);
}
__device__ __forceinline__ void cp16(uint32_t dst, const void* src) {
    asm volatile("cp.async.cg.shared.global [%0], [%1], 16;" :: "r"(dst), "l"(src));
}
#define CP_COMMIT  asm volatile("cp.async.commit_group;" ::: "memory")
#define CP_WAIT(n) asm volatile("cp.async.wait_group %0;" :: "n"(n) : "memory")

// ---------------- fp32 -> tf32 hi/lo split (one-time) ----------------
__global__ void split_arr(const float4* __restrict__ src,
                          uint4* __restrict__ hi, uint4* __restrict__ lo, int n4)
{
    int i = blockIdx.x * 256 + threadIdx.x;
    if (i >= n4) return;
    float4 v = src[i];
    uint4 h, l;
    split_tf(v.x, h.x, l.x); split_tf(v.y, h.y, l.y);
    split_tf(v.z, h.z, l.z); split_tf(v.w, h.w, l.w);
    hi[i] = h; lo[i] = l;
}

// ======================================================================
// 3xTF32 GEMM on pre-split operands, cp.async double-buffered.
// C[M,N] = A[M,K] @ B[K,N] + bias. 256 thr / 8 warps, tile 128x128, BK=32.
// TFOUT=0: C float (+bias). TFOUT=1: C uint32 tf32 of (acc+bias)*prescale.
// gridDim.z selects operand set 0/1 (fused K/V projection).
// ======================================================================
#define SA 36     /* A smem stride (u32): frag bank 4g+t, bijective */
#define SB 136    /* B smem stride (u32): frag bank 8t+g, bijective */
#define ASTG (128*SA)   /* 4608 u32 per A buffer */
#define BSTG (32*SB)    /* 4352 u32 per B buffer */
#define GEMM_SMEM ((2*ASTG*2 + 2*BSTG*2) * 4)   /* 143360 B */

template<int TFOUT>
__global__ __launch_bounds__(256) void gemm_ds(
    const uint32_t* __restrict__ Ah, const uint32_t* __restrict__ Al,
    const uint32_t* __restrict__ Bh0, const uint32_t* __restrict__ Bl0,
    const float* __restrict__ bias0, void* __restrict__ C0,
    const uint32_t* __restrict__ Bh1, const uint32_t* __restrict__ Bl1,
    const float* __restrict__ bias1, void* __restrict__ C1,
    int N, int K, float prescale)
{
    extern __shared__ uint32_t smg[];
    uint32_t* sAh = smg;                 // 2 x ASTG
    uint32_t* sAl = sAh + 2*ASTG;
    uint32_t* sBh = sAl + 2*ASTG;        // 2 x BSTG
    uint32_t* sBl = sBh + 2*BSTG;
    const uint32_t aAh = s2u(sAh), aAl = s2u(sAl);
    const uint32_t aBh = s2u(sBh), aBl = s2u(sBl);

    const uint32_t* Bh   = blockIdx.z ? Bh1   : Bh0;
    const uint32_t* Bl   = blockIdx.z ? Bl1   : Bl0;
    const float*    bias = blockIdx.z ? bias1 : bias0;
    void*           C    = blockIdx.z ? C1    : C0;

    const int tid  = threadIdx.x;
    const int lane = tid & 31, warp = tid >> 5;
    const int g = lane >> 2, t = lane & 3;
    const int wm = (warp >> 1) * 32;
    const int wn = (warp & 1) * 64;
    const int row0 = blockIdx.y * 128;
    const int col0 = blockIdx.x * 128;

    float acc[2][8][4];
    #pragma unroll
    for (int i = 0; i < 2; i++)
        #pragma unroll
        for (int j = 0; j < 8; j++)
            #pragma unroll
            for (int c = 0; c < 4; c++) acc[i][j][c] = 0.f;

    auto load_stage = [&](int k0, int st) {
        // A tiles: 128 rows x 32 u32, 8 chunks/row -> 1024 chunks each
        #pragma unroll
        for (int j = 0; j < 4; j++) {
            int idx = tid + j * 256;
            int r = idx >> 3, c = (idx & 7) * 4;
            size_t go = (size_t)(row0 + r) * K + k0 + c;
            uint32_t so = (uint32_t)(st * ASTG + r * SA + c) * 4;
            cp16(aAh + so, Ah + go);
            cp16(aAl + so, Al + go);
        }
        // B tiles: 32 rows x 128 u32
        #pragma unroll
        for (int j = 0; j < 4; j++) {
            int idx = tid + j * 256;
            int r = idx >> 5, c = (idx & 31) * 4;
            size_t go = (size_t)(k0 + r) * N + col0 + c;
            uint32_t so = (uint32_t)(st * BSTG + r * SB + c) * 4;
            cp16(aBh + so, Bh + go);
            cp16(aBl + so, Bl + go);
        }
    };

    const int NIT = K / 32;
    load_stage(0, 0); CP_COMMIT;

    for (int it = 0; it < NIT; ++it) {
        const int st = it & 1;
        if (it + 1 < NIT) { load_stage((it + 1) * 32, st ^ 1); CP_COMMIT; CP_WAIT(1); }
        else              { CP_WAIT(0); }
        __syncthreads();

        const uint32_t* Ah_s = sAh + st * ASTG;
        const uint32_t* Al_s = sAl + st * ASTG;
        const uint32_t* Bh_s = sBh + st * BSTG;
        const uint32_t* Bl_s = sBl + st * BSTG;

        #pragma unroll
        for (int s = 0; s < 4; s++) {
            const int kb = s * 8;
            uint32_t ah[2][4], al[2][4];
            #pragma unroll
            for (int mt = 0; mt < 2; mt++) {
                int rm = wm + mt * 16 + g;
                ah[mt][0] = Ah_s[rm * SA + kb + t];
                ah[mt][1] = Ah_s[(rm + 8) * SA + kb + t];
                ah[mt][2] = Ah_s[rm * SA + kb + t + 4];
                ah[mt][3] = Ah_s[(rm + 8) * SA + kb + t + 4];
                al[mt][0] = Al_s[rm * SA + kb + t];
                al[mt][1] = Al_s[(rm + 8) * SA + kb + t];
                al[mt][2] = Al_s[rm * SA + kb + t + 4];
                al[mt][3] = Al_s[(rm + 8) * SA + kb + t + 4];
            }
            #pragma unroll
            for (int nt = 0; nt < 8; nt++) {
                int cn = wn + nt * 8 + g;
                uint32_t bh0 = Bh_s[(kb + t) * SB + cn];
                uint32_t bh1 = Bh_s[(kb + t + 4) * SB + cn];
                uint32_t bl0 = Bl_s[(kb + t) * SB + cn];
                uint32_t bl1 = Bl_s[(kb + t + 4) * SB + cn];
                #pragma unroll
                for (int mt = 0; mt < 2; mt++) {
                    mma8(acc[mt][nt], ah[mt], bh0, bh1);   // hi*hi
                    mma8(acc[mt][nt], al[mt], bh0, bh1);   // lo*hi
                    mma8(acc[mt][nt], ah[mt], bl0, bl1);   // hi*lo
                }
            }
        }
        __syncthreads();
    }

    #pragma unroll
    for (int mt = 0; mt < 2; mt++) {
        int row = row0 + wm + mt * 16 + g;
        #pragma unroll
        for (int nt = 0; nt < 8; nt++) {
            int col = col0 + wn + nt * 8 + 2 * t;
            float bx = bias[col], by = bias[col + 1];
            float v00 = acc[mt][nt][0] + bx, v01 = acc[mt][nt][1] + by;
            float v10 = acc[mt][nt][2] + bx, v11 = acc[mt][nt][3] + by;
            if (TFOUT) {
                uint32_t* Cu = (uint32_t*)C;
                uint2 a = { f2tf(v00 * prescale), f2tf(v01 * prescale) };
                uint2 b = { f2tf(v10 * prescale), f2tf(v11 * prescale) };
                *(uint2*)(Cu + (size_t)row * N + col)       = a;
                *(uint2*)(Cu + (size_t)(row + 8) * N + col) = b;
            } else {
                float* Cf = (float*)C;
                *(float2*)(Cf + (size_t)row * N + col)       = make_float2(v00, v01);
                *(float2*)(Cf + (size_t)(row + 8) * N + col) = make_float2(v10, v11);
            }
        }
    }
}

// ======================================================================
// Flash attention, tf32 mma, pre-converted operands, cp.async pipeline.
// Block = (b, h, 128-q-row tile), 256 thr. Warp w owns q rows [16w,16w+16).
// K double-buffered; V single-buffered (load overlaps next QK).
// ======================================================================
#define SQm 132
#define SKm 132
#define SVm 136
#define SPm 68
#define ATTN_SMEM ((128*SQm + 2*64*SKm + 64*SVm + 128*SPm) * 4)   /* 204800 B */

__global__ __launch_bounds__(256) void attn_tf32(
    const uint32_t* __restrict__ Qt, const uint32_t* __restrict__ Kt,
    const uint32_t* __restrict__ Vt,
    uint32_t* __restrict__ OutH, uint32_t* __restrict__ OutL)
{
    extern __shared__ uint32_t sm[];
    uint32_t* Qs = sm;                    // 128 x SQm
    uint32_t* Ks = Qs + 128 * SQm;        // 2 x 64 x SKm
    uint32_t* Vs = Ks + 2 * 64 * SKm;     // 64 x SVm
    uint32_t* Ps = Vs + 64 * SVm;         // 128 x SPm
    const uint32_t aQ = s2u(Qs), aK = s2u(Ks), aV = s2u(Vs);

    const int tid  = threadIdx.x;
    const int lane = tid & 31, warp = tid >> 5;
    const int g = lane >> 2, t = lane & 3;
    const int qt = blockIdx.x, h = blockIdx.y, b = blockIdx.z;

    const size_t qbase = ((size_t)(b * SEQ + qt * 128)) * HID + h * HD;
    const size_t kvb   = (size_t)b * SEQ * HD;

    auto load_K = [&](int tile, int st) {
        #pragma unroll
        for (int j = 0; j < 8; j++) {
            int idx = tid + j * 256;
            int r = idx >> 5, c = (idx & 31) * 4;
            cp16(aK + (uint32_t)(st * 64 * SKm + r * SKm + c) * 4,
                 Kt + kvb + (size_t)(tile * 64 + r) * HD + c);
        }
    };
    auto load_V = [&](int tile) {
        #pragma unroll
        for (int j = 0; j < 8; j++) {
            int idx = tid + j * 256;
            int r = idx >> 5, c = (idx & 31) * 4;
            cp16(aV + (uint32_t)(r * SVm + c) * 4,
                 Vt + kvb + (size_t)(tile * 64 + r) * HD + c);
        }
    };

    // prologue: Q + K0 + V0 in one group
    #pragma unroll
    for (int j = 0; j < 16; j++) {
        int idx = tid + j * 256;
        int r = idx >> 5, c = (idx & 31) * 4;
        cp16(aQ + (uint32_t)(r * SQm + c) * 4, Qt + qbase + (size_t)r * HID + c);
    }
    load_K(0, 0);
    load_V(0);
    CP_COMMIT;

    float mrow[2] = { -1e30f, -1e30f };
    float lrow[2] = { 0.f, 0.f };
    float o[16][4];
    #pragma unroll
    for (int nt = 0; nt < 16; nt++)
        #pragma unroll
        for (int c = 0; c < 4; c++) o[nt][c] = 0.f;

    const int prow0 = (warp * 16 + g) * SPm;
    const int prow1 = prow0 + 8 * SPm;
    const int NT = SEQ / 64;

    for (int kt = 0; kt < NT; kt++) {
        if (kt == 0) { CP_WAIT(0); } else { CP_WAIT(1); }   // K(kt) ready
        __syncthreads();

        // ---- S(16x64) = Q_warp @ K^T ----
        const uint32_t* Kst = Ks + (kt & 1) * 64 * SKm;
        float s[8][4];
        #pragma unroll
        for (int nt = 0; nt < 8; nt++)
            #pragma unroll
            for (int c = 0; c < 4; c++) s[nt][c] = 0.f;

        #pragma unroll
        for (int ks = 0; ks < 16; ks++) {
            const int kb = ks * 8;
            const int rm = warp * 16 + g;
            uint32_t a[4];
            a[0] = Qs[rm * SQm + kb + t];
            a[1] = Qs[(rm + 8) * SQm + kb + t];
            a[2] = Qs[rm * SQm + kb + t + 4];
            a[3] = Qs[(rm + 8) * SQm + kb + t + 4];
            #pragma unroll
            for (int nt = 0; nt < 8; nt++) {
                int cn = nt * 8 + g;
                uint32_t b0 = Kst[cn * SKm + kb + t];
                uint32_t b1 = Kst[cn * SKm + kb + t + 4];
                mma8(s[nt], a, b0, b1);
            }
        }

        // prefetch K(kt+1) into the other K buffer (overlaps softmax + PV)
        if (kt + 1 < NT) { load_K(kt + 1, (kt + 1) & 1); CP_COMMIT; }

        // ---- online softmax ----
        float tm0 = -1e30f, tm1 = -1e30f;
        #pragma unroll
        for (int nt = 0; nt < 8; nt++) {
            tm0 = fmaxf(tm0, fmaxf(s[nt][0], s[nt][1]));
            tm1 = fmaxf(tm1, fmaxf(s[nt][2], s[nt][3]));
        }
        tm0 = fmaxf(tm0, __shfl_xor_sync(0xffffffffu, tm0, 1));
        tm0 = fmaxf(tm0, __shfl_xor_sync(0xffffffffu, tm0, 2));
        tm1 = fmaxf(tm1, __shfl_xor_sync(0xffffffffu, tm1, 1));
        tm1 = fmaxf(tm1, __shfl_xor_sync(0xffffffffu, tm1, 2));

        float mn0 = fmaxf(mrow[0], tm0), mn1 = fmaxf(mrow[1], tm1);
        float f0 = __expf(mrow[0] - mn0), f1 = __expf(mrow[1] - mn1);
        mrow[0] = mn0; mrow[1] = mn1;
        lrow[0] *= f0; lrow[1] *= f1;
        #pragma unroll
        for (int nt = 0; nt < 16; nt++) {
            o[nt][0] *= f0; o[nt][1] *= f0;
            o[nt][2] *= f1; o[nt][3] *= f1;
        }

        float ps0 = 0.f, ps1 = 0.f;
        #pragma unroll
        for (int nt = 0; nt < 8; nt++) {
            int col = nt * 8 + 2 * t;
            float p0 = __expf(s[nt][0] - mn0); ps0 += p0;
            float p1 = __expf(s[nt][1] - mn0); ps0 += p1;
            float p2 = __expf(s[nt][2] - mn1); ps1 += p2;
            float p3 = __expf(s[nt][3] - mn1); ps1 += p3;
            Ps[prow0 + col]     = f2tf(p0);
            Ps[prow0 + col + 1] = f2tf(p1);
            Ps[prow1 + col]     = f2tf(p2);
            Ps[prow1 + col + 1] = f2tf(p3);
        }
        ps0 += __shfl_xor_sync(0xffffffffu, ps0, 1);
        ps0 += __shfl_xor_sync(0xffffffffu, ps0, 2);
        ps1 += __shfl_xor_sync(0xffffffffu, ps1, 1);
        ps1 += __shfl_xor_sync(0xffffffffu, ps1, 2);
        lrow[0] += ps0; lrow[1] += ps1;
        __syncwarp();

        // V(kt) ready (all but the newest K group drained)
        if (kt + 1 < NT) { CP_WAIT(1); } else { CP_WAIT(0); }
        __syncthreads();

        // ---- O(16x128) += P(16x64) @ V(64x128) ----
        #pragma unroll
        for (int ks = 0; ks < 8; ks++) {
            const int kb = ks * 8;
            uint32_t a[4];
            a[0] = Ps[prow0 + kb + t];
            a[1] = Ps[prow1 + kb + t];
            a[2] = Ps[prow0 + kb + t + 4];
            a[3] = Ps[prow1 + kb + t + 4];
            #pragma unroll
            for (int nt = 0; nt < 16; nt++) {
                int cn = nt * 8 + g;
                uint32_t b0 = Vs[(kb + t) * SVm + cn];
                uint32_t b1 = Vs[(kb + t + 4) * SVm + cn];
                mma8(o[nt], a, b0, b1);
            }
        }
        __syncthreads();   // all warps done with V(kt) before overwrite
        if (kt + 1 < NT) { load_V(kt + 1); CP_COMMIT; }
    }

    // epilogue: normalize + split hi/lo for the O-projection
    float inv0 = 1.f / lrow[0], inv1 = 1.f / lrow[1];
    const size_t ob = ((size_t)(b * SEQ + qt * 128 + warp * 16 + g)) * HID + h * HD;
    #pragma unroll
    for (int nt = 0; nt < 16; nt++) {
        int col = nt * 8 + 2 * t;
        float v00 = o[nt][0] * inv0, v01 = o[nt][1] * inv0;
        float v10 = o[nt][2] * inv1, v11 = o[nt][3] * inv1;
        uint2 h0, l0, h1, l1;
        split_tf(v00, h0.x, l0.x); split_tf(v01, h0.y, l0.y);
        split_tf(v10, h1.x, l1.x); split_tf(v11, h1.y, l1.y);
        *(uint2*)(OutH + ob + col)           = h0;
        *(uint2*)(OutL + ob + col)           = l0;
        *(uint2*)(OutH + ob + 8 * HID + col) = h1;
        *(uint2*)(OutL + ob + 8 * HID + col) = l1;
    }
}

// ---------------- launch ----------------
extern "C" void kernel_launch(void* const* d_in, const int* in_sizes, int n_in,
                              void* d_out, int out_size)
{
    const float* hidden = (const float*)d_in[0];
    const float* Wq = (const float*)d_in[1];
    const float* bq = (const float*)d_in[2];
    const float* Wk = (const float*)d_in[3];
    const float* bk = (const float*)d_in[4];
    const float* Wv = (const float*)d_in[5];
    const float* bv = (const float*)d_in[6];
    const float* Wo = (const float*)d_in[7];
    const float* bo = (const float*)d_in[8];
    float* out = (float*)d_out;

    uint32_t *Hh, *Hl, *Wqh, *Wql, *Woh, *Wol, *Wkh, *Wkl, *Wvh, *Wvl;
    uint32_t *Qtp, *Ktp, *Vtp, *Ahp, *Alp;
    cudaGetSymbolAddress((void**)&Hh,  g_Hh);  cudaGetSymbolAddress((void**)&Hl,  g_Hl);
    cudaGetSymbolAddress((void**)&Wqh, g_Wqh); cudaGetSymbolAddress((void**)&Wql, g_Wql);
    cudaGetSymbolAddress((void**)&Woh, g_Woh); cudaGetSymbolAddress((void**)&Wol, g_Wol);
    cudaGetSymbolAddress((void**)&Wkh, g_Wkh); cudaGetSymbolAddress((void**)&Wkl, g_Wkl);
    cudaGetSymbolAddress((void**)&Wvh, g_Wvh); cudaGetSymbolAddress((void**)&Wvl, g_Wvl);
    cudaGetSymbolAddress((void**)&Qtp, g_Qt);
    cudaGetSymbolAddress((void**)&Ktp, g_Kt);  cudaGetSymbolAddress((void**)&Vtp, g_Vt);
    cudaGetSymbolAddress((void**)&Ahp, g_Ah);  cudaGetSymbolAddress((void**)&Alp, g_Al);

    cudaFuncSetAttribute(gemm_ds<0>, cudaFuncAttributeMaxDynamicSharedMemorySize, GEMM_SMEM);
    cudaFuncSetAttribute(gemm_ds<1>, cudaFuncAttributeMaxDynamicSharedMemorySize, GEMM_SMEM);
    cudaFuncSetAttribute(attn_tf32,  cudaFuncAttributeMaxDynamicSharedMemorySize, ATTN_SMEM);

    const float scale = 0.08838834764831845f;   // 1/sqrt(128)

    // one-time splits
    split_arr<<<(MTOT*HID/4 + 255)/256, 256>>>((const float4*)hidden, (uint4*)Hh,  (uint4*)Hl,  MTOT*HID/4);
    split_arr<<<(HID*HID/4  + 255)/256, 256>>>((const float4*)Wq,     (uint4*)Wqh, (uint4*)Wql, HID*HID/4);
    split_arr<<<(HID*HD/4   + 255)/256, 256>>>((const float4*)Wk,     (uint4*)Wkh, (uint4*)Wkl, HID*HD/4);
    split_arr<<<(HID*HD/4   + 255)/256, 256>>>((const float4*)Wv,     (uint4*)Wvh, (uint4*)Wvl, HID*HD/4);
    split_arr<<<(HID*HID/4  + 255)/256, 256>>>((const float4*)Wo,     (uint4*)Woh, (uint4*)Wol, HID*HID/4);

    // K / V projections fused (tf32 out), N=128
    {
        dim3 grid(1, MTOT / 128, 2);
        gemm_ds<1><<<grid, 256, GEMM_SMEM>>>(Hh, Hl,
                                             Wkh, Wkl, bk, Ktp,
                                             Wvh, Wvl, bv, Vtp,
                                             HD, HID, 1.0f);
    }
    // Q projection (tf32 out, scale folded)
    {
        dim3 grid(HID / 128, MTOT / 128, 1);
        gemm_ds<1><<<grid, 256, GEMM_SMEM>>>(Hh, Hl,
                                             Wqh, Wql, bq, Qtp,
                                             Wqh, Wql, bq, Qtp,
                                             HID, HID, scale);
    }
    // attention
    {
        dim3 grid(SEQ / 128, NH, BATCH);
        attn_tf32<<<grid, 256, ATTN_SMEM>>>(Qtp, Ktp, Vtp, Ahp, Alp);
    }
    // O projection (fp32 out) -> d_out
    {
        dim3 grid(HID / 128, MTOT / 128, 1);
        gemm_ds<0><<<grid, 256, GEMM_SMEM>>>(Ahp, Alp,
                                             Woh, Wol, bo, out,
                                             Woh, Wol, bo, out,
                                             HID, HID, 1.0f);
    }
}

// round 11
// speedup vs baseline: 3.3368x; 1.0433x over previous
#include <cuda_runtime.h>
#include <cstdint>

#define HID 2048
#define SEQ 2048
#define BATCH 2
#define NH 16
#define HD 128
#define MTOT (BATCH*SEQ)   /* 4096 */
#define HID2 (HID/2)

// ---------------- scratch (no allocations allowed) ----------------
__device__ uint32_t g_Hh[MTOT*HID2],  g_Hl[MTOT*HID2];    // hidden, bf16x2 packed along K
__device__ uint32_t g_Wqh[HID2*HID],  g_Wql[HID2*HID];    // weights, packed along K
__device__ uint32_t g_Woh[HID2*HID],  g_Wol[HID2*HID];
__device__ uint32_t g_Wkh[HID2*HD],   g_Wkl[HID2*HD];
__device__ uint32_t g_Wvh[HID2*HD],   g_Wvl[HID2*HD];
__device__ uint32_t g_Qt[MTOT*HID];                       // Q tf32, scale folded
__device__ uint32_t g_Kt[MTOT*HD],    g_Vt[MTOT*HD];      // K,V tf32
__device__ uint32_t g_Ah[MTOT*HID2],  g_Al[MTOT*HID2];    // attn out, bf16x2 packed

// ---------------- numeric helpers ----------------
__device__ __forceinline__ uint32_t f2tf(float x) {
    uint32_t r; asm("cvt.rna.tf32.f32 %0, %1;" : "=r"(r) : "f"(x)); return r;
}
__device__ __forceinline__ uint16_t f2bf(float x) {
    uint16_t r; asm("cvt.rn.bf16.f32 %0, %1;" : "=h"(r) : "f"(x)); return r;
}
__device__ __forceinline__ float bf2f(uint16_t b) {
    return __uint_as_float(((uint32_t)b) << 16);
}
// pack two fp32 into bf16x2 hi-part and residual lo-part (low half = first arg)
__device__ __forceinline__ void packsplit_bf(float x0, float x1, uint32_t &hi, uint32_t &lo) {
    uint16_t h0 = f2bf(x0), h1 = f2bf(x1);
    hi = (uint32_t)h0 | ((uint32_t)h1 << 16);
    uint16_t l0 = f2bf(x0 - bf2f(h0)), l1 = f2bf(x1 - bf2f(h1));
    lo = (uint32_t)l0 | ((uint32_t)l1 << 16);
}
// tf32 mma m16n8k8
__device__ __forceinline__ void mma8(float* d, const uint32_t* a, uint32_t b0, uint32_t b1) {
    asm volatile(
        "mma.sync.aligned.m16n8k8.row.col.f32.tf32.tf32.f32 "
        "{%0,%1,%2,%3}, {%4,%5,%6,%7}, {%8,%9}, {%0,%1,%2,%3};"
        : "+f"(d[0]), "+f"(d[1]), "+f"(d[2]), "+f"(d[3])
        : "r"(a[0]), "r"(a[1]), "r"(a[2]), "r"(a[3]), "r"(b0), "r"(b1));
}
// bf16 mma m16n8k16 (2x MACs per instruction)
__device__ __forceinline__ void mma16(float* d, const uint32_t* a, uint32_t b0, uint32_t b1) {
    asm volatile(
        "mma.sync.aligned.m16n8k16.row.col.f32.bf16.bf16.f32 "
        "{%0,%1,%2,%3}, {%4,%5,%6,%7}, {%8,%9}, {%0,%1,%2,%3};"
        : "+f"(d[0]), "+f"(d[1]), "+f"(d[2]), "+f"(d[3])
        : "r"(a[0]), "r"(a[1]), "r"(a[2]), "r"(a[3]), "r"(b0), "r"(b1));
}
__device__ __forceinline__ uint32_t s2u(const void* p) {
    return (uint32_t)__cvta_generic_to_shared(p);
}
__device__ __forceinline__ void cp16(uint32_t dst, const void* src) {
    asm volatile("cp.async.cg.shared.global [%0], [%1], 16;" :: "r"(dst), "l"(src));
}
#define CP_COMMIT  asm volatile("cp.async.commit_group;" ::: "memory")
#define CP_WAIT(n) asm volatile("cp.async.wait_group %0;" :: "n"(n) : "memory")

// ---------------- one-time packers ----------------
// contiguous pairs along last dim (hidden): out[i] packs src[2i],src[2i+1]
__global__ void packA_bf(const float2* __restrict__ src,
                         uint32_t* __restrict__ hi, uint32_t* __restrict__ lo, int n2)
{
    int i = blockIdx.x * 256 + threadIdx.x;
    if (i >= n2) return;
    float2 v = src[i];
    packsplit_bf(v.x, v.y, hi[i], lo[i]);
}
// weights [K][N]: pack along K (rows 2kp, 2kp+1) -> out[kp*N + n]
__global__ void packB_bf(const float* __restrict__ W,
                         uint32_t* __restrict__ hi, uint32_t* __restrict__ lo,
                         int N, int tot)
{
    int i = blockIdx.x * 256 + threadIdx.x;
    if (i >= tot) return;
    int kp = i / N, n = i - kp * N;
    float x0 = W[(size_t)(2 * kp) * N + n];
    float x1 = W[(size_t)(2 * kp + 1) * N + n];
    packsplit_bf(x0, x1, hi[i], lo[i]);
}

// ======================================================================
// bf16x3 GEMM on packed operands, cp.async double-buffered, 2 CTAs/SM.
// C[M,N] = A[M,K] @ B[K,N] + bias (fp32-class accuracy via hi/lo split).
// A packed [M][K/2] u32, B packed [K/2][N] u32. 256 thr, tile 128x128, BK=32.
// TFOUT=0: C float (+bias). TFOUT=1: C uint32 tf32 of (acc+bias)*prescale.
// gridDim.z selects operand set 0/1 (fused K/V projection).
// ======================================================================
#define SA 20     /* A smem stride (u32): 20%32=4 -> frag bank bijective */
#define SB 136    /* B smem stride (u32): 136%32=8 -> frag bank bijective */
#define ASTG (128*SA)   /* 2560 u32 per A stage */
#define BSTG (16*SB)    /* 2176 u32 per B stage */
#define GEMM_SMEM ((2*ASTG*2 + 2*BSTG*2) * 4)   /* 75776 B -> 2 CTAs/SM */

template<int TFOUT>
__global__ __launch_bounds__(256, 2) void gemm_bf3(
    const uint32_t* __restrict__ Ahp, const uint32_t* __restrict__ Alp,
    const uint32_t* __restrict__ Bh0, const uint32_t* __restrict__ Bl0,
    const float* __restrict__ bias0, void* __restrict__ C0,
    const uint32_t* __restrict__ Bh1, const uint32_t* __restrict__ Bl1,
    const float* __restrict__ bias1, void* __restrict__ C1,
    int N, int K, float prescale)
{
    extern __shared__ uint32_t smg[];
    uint32_t* sAh = smg;                 // 2 x ASTG
    uint32_t* sAl = sAh + 2*ASTG;
    uint32_t* sBh = sAl + 2*ASTG;        // 2 x BSTG
    uint32_t* sBl = sBh + 2*BSTG;
    const uint32_t aAh = s2u(sAh), aAl = s2u(sAl);
    const uint32_t aBh = s2u(sBh), aBl = s2u(sBl);

    const uint32_t* Bh   = blockIdx.z ? Bh1   : Bh0;
    const uint32_t* Bl   = blockIdx.z ? Bl1   : Bl0;
    const float*    bias = blockIdx.z ? bias1 : bias0;
    void*           C    = blockIdx.z ? C1    : C0;

    const int tid  = threadIdx.x;
    const int lane = tid & 31, warp = tid >> 5;
    const int g = lane >> 2, t = lane & 3;
    const int wm = (warp >> 1) * 32;
    const int wn = (warp & 1) * 64;
    const int row0 = blockIdx.y * 128;
    const int col0 = blockIdx.x * 128;
    const int K2 = K >> 1;

    float acc[2][8][4];
    #pragma unroll
    for (int i = 0; i < 2; i++)
        #pragma unroll
        for (int j = 0; j < 8; j++)
            #pragma unroll
            for (int c = 0; c < 4; c++) acc[i][j][c] = 0.f;

    auto load_stage = [&](int kp0, int st) {
        // A: 128 rows x 16 u32 -> 512 float4 chunks per array
        #pragma unroll
        for (int j = 0; j < 2; j++) {
            int idx = tid + j * 256;
            int r = idx >> 2, c = (idx & 3) * 4;
            size_t go = (size_t)(row0 + r) * K2 + kp0 + c;
            uint32_t so = (uint32_t)(st * ASTG + r * SA + c) * 4;
            cp16(aAh + so, Ahp + go);
            cp16(aAl + so, Alp + go);
        }
        // B: 16 rows x 128 u32 -> 512 chunks per array
        #pragma unroll
        for (int j = 0; j < 2; j++) {
            int idx = tid + j * 256;
            int r = idx >> 5, c = (idx & 31) * 4;
            size_t go = (size_t)(kp0 + r) * N + col0 + c;
            uint32_t so = (uint32_t)(st * BSTG + r * SB + c) * 4;
            cp16(aBh + so, Bh + go);
            cp16(aBl + so, Bl + go);
        }
    };

    const int NIT = K / 32;              // 16 packed rows per iter
    load_stage(0, 0); CP_COMMIT;

    for (int it = 0; it < NIT; ++it) {
        const int st = it & 1;
        if (it + 1 < NIT) { load_stage((it + 1) * 16, st ^ 1); CP_COMMIT; CP_WAIT(1); }
        else              { CP_WAIT(0); }
        __syncthreads();

        const uint32_t* Ah_s = sAh + st * ASTG;
        const uint32_t* Al_s = sAl + st * ASTG;
        const uint32_t* Bh_s = sBh + st * BSTG;
        const uint32_t* Bl_s = sBl + st * BSTG;

        #pragma unroll
        for (int s = 0; s < 2; s++) {            // two k16 steps per BK=32
            const int kb = s * 8;                // packed-u32 offset
            uint32_t ah[2][4], al[2][4];
            #pragma unroll
            for (int mt = 0; mt < 2; mt++) {
                int rm = wm + mt * 16 + g;
                ah[mt][0] = Ah_s[rm * SA + kb + t];
                ah[mt][1] = Ah_s[(rm + 8) * SA + kb + t];
                ah[mt][2] = Ah_s[rm * SA + kb + t + 4];
                ah[mt][3] = Ah_s[(rm + 8) * SA + kb + t + 4];
                al[mt][0] = Al_s[rm * SA + kb + t];
                al[mt][1] = Al_s[(rm + 8) * SA + kb + t];
                al[mt][2] = Al_s[rm * SA + kb + t + 4];
                al[mt][3] = Al_s[(rm + 8) * SA + kb + t + 4];
            }
            #pragma unroll
            for (int nt = 0; nt < 8; nt++) {
                int cn = wn + nt * 8 + g;
                uint32_t bh0 = Bh_s[(kb + t) * SB + cn];
                uint32_t bh1 = Bh_s[(kb + t + 4) * SB + cn];
                uint32_t bl0 = Bl_s[(kb + t) * SB + cn];
                uint32_t bl1 = Bl_s[(kb + t + 4) * SB + cn];
                #pragma unroll
                for (int mt = 0; mt < 2; mt++) {
                    mma16(acc[mt][nt], ah[mt], bh0, bh1);   // hi*hi
                    mma16(acc[mt][nt], al[mt], bh0, bh1);   // lo*hi
                    mma16(acc[mt][nt], ah[mt], bl0, bl1);   // hi*lo
                }
            }
        }
        __syncthreads();
    }

    #pragma unroll
    for (int mt = 0; mt < 2; mt++) {
        int row = row0 + wm + mt * 16 + g;
        #pragma unroll
        for (int nt = 0; nt < 8; nt++) {
            int col = col0 + wn + nt * 8 + 2 * t;
            float bx = bias[col], by = bias[col + 1];
            float v00 = acc[mt][nt][0] + bx, v01 = acc[mt][nt][1] + by;
            float v10 = acc[mt][nt][2] + bx, v11 = acc[mt][nt][3] + by;
            if (TFOUT) {
                uint32_t* Cu = (uint32_t*)C;
                uint2 a = { f2tf(v00 * prescale), f2tf(v01 * prescale) };
                uint2 b = { f2tf(v10 * prescale), f2tf(v11 * prescale) };
                *(uint2*)(Cu + (size_t)row * N + col)       = a;
                *(uint2*)(Cu + (size_t)(row + 8) * N + col) = b;
            } else {
                float* Cf = (float*)C;
                *(float2*)(Cf + (size_t)row * N + col)       = make_float2(v00, v01);
                *(float2*)(Cf + (size_t)(row + 8) * N + col) = make_float2(v10, v11);
            }
        }
    }
}

// ======================================================================
// Flash attention, tf32 mma, pre-converted operands, cp.async pipeline.
// Block = (b, h, 128-q-row tile), 256 thr. Warp w owns q rows [16w,16w+16).
// K double-buffered; V single-buffered. Epilogue emits packed-bf16 hi/lo.
// ======================================================================
#define SQm 132
#define SKm 132
#define SVm 136
#define SPm 68
#define ATTN_SMEM ((128*SQm + 2*64*SKm + 64*SVm + 128*SPm) * 4)   /* 204800 B */

__global__ __launch_bounds__(256) void attn_tf32(
    const uint32_t* __restrict__ Qt, const uint32_t* __restrict__ Kt,
    const uint32_t* __restrict__ Vt,
    uint32_t* __restrict__ OutH, uint32_t* __restrict__ OutL)
{
    extern __shared__ uint32_t sm[];
    uint32_t* Qs = sm;                    // 128 x SQm
    uint32_t* Ks = Qs + 128 * SQm;        // 2 x 64 x SKm
    uint32_t* Vs = Ks + 2 * 64 * SKm;     // 64 x SVm
    uint32_t* Ps = Vs + 64 * SVm;         // 128 x SPm
    const uint32_t aQ = s2u(Qs), aK = s2u(Ks), aV = s2u(Vs);

    const int tid  = threadIdx.x;
    const int lane = tid & 31, warp = tid >> 5;
    const int g = lane >> 2, t = lane & 3;
    const int qt = blockIdx.x, h = blockIdx.y, b = blockIdx.z;

    const size_t qbase = ((size_t)(b * SEQ + qt * 128)) * HID + h * HD;
    const size_t kvb   = (size_t)b * SEQ * HD;

    auto load_K = [&](int tile, int st) {
        #pragma unroll
        for (int j = 0; j < 8; j++) {
            int idx = tid + j * 256;
            int r = idx >> 5, c = (idx & 31) * 4;
            cp16(aK + (uint32_t)(st * 64 * SKm + r * SKm + c) * 4,
                 Kt + kvb + (size_t)(tile * 64 + r) * HD + c);
        }
    };
    auto load_V = [&](int tile) {
        #pragma unroll
        for (int j = 0; j < 8; j++) {
            int idx = tid + j * 256;
            int r = idx >> 5, c = (idx & 31) * 4;
            cp16(aV + (uint32_t)(r * SVm + c) * 4,
                 Vt + kvb + (size_t)(tile * 64 + r) * HD + c);
        }
    };

    // prologue: Q + K0 + V0 in one group
    #pragma unroll
    for (int j = 0; j < 16; j++) {
        int idx = tid + j * 256;
        int r = idx >> 5, c = (idx & 31) * 4;
        cp16(aQ + (uint32_t)(r * SQm + c) * 4, Qt + qbase + (size_t)r * HID + c);
    }
    load_K(0, 0);
    load_V(0);
    CP_COMMIT;

    float mrow[2] = { -1e30f, -1e30f };
    float lrow[2] = { 0.f, 0.f };
    float o[16][4];
    #pragma unroll
    for (int nt = 0; nt < 16; nt++)
        #pragma unroll
        for (int c = 0; c < 4; c++) o[nt][c] = 0.f;

    const int prow0 = (warp * 16 + g) * SPm;
    const int prow1 = prow0 + 8 * SPm;
    const int NT = SEQ / 64;

    for (int kt = 0; kt < NT; kt++) {
        if (kt == 0) { CP_WAIT(0); } else { CP_WAIT(1); }   // K(kt) ready
        __syncthreads();

        // ---- S(16x64) = Q_warp @ K^T ----
        const uint32_t* Kst = Ks + (kt & 1) * 64 * SKm;
        float s[8][4];
        #pragma unroll
        for (int nt = 0; nt < 8; nt++)
            #pragma unroll
            for (int c = 0; c < 4; c++) s[nt][c] = 0.f;

        #pragma unroll
        for (int ks = 0; ks < 16; ks++) {
            const int kb = ks * 8;
            const int rm = warp * 16 + g;
            uint32_t a[4];
            a[0] = Qs[rm * SQm + kb + t];
            a[1] = Qs[(rm + 8) * SQm + kb + t];
            a[2] = Qs[rm * SQm + kb + t + 4];
            a[3] = Qs[(rm + 8) * SQm + kb + t + 4];
            #pragma unroll
            for (int nt = 0; nt < 8; nt++) {
                int cn = nt * 8 + g;
                uint32_t b0 = Kst[cn * SKm + kb + t];
                uint32_t b1 = Kst[cn * SKm + kb + t + 4];
                mma8(s[nt], a, b0, b1);
            }
        }

        // prefetch K(kt+1) (overlaps softmax + PV)
        if (kt + 1 < NT) { load_K(kt + 1, (kt + 1) & 1); CP_COMMIT; }

        // ---- online softmax ----
        float tm0 = -1e30f, tm1 = -1e30f;
        #pragma unroll
        for (int nt = 0; nt < 8; nt++) {
            tm0 = fmaxf(tm0, fmaxf(s[nt][0], s[nt][1]));
            tm1 = fmaxf(tm1, fmaxf(s[nt][2], s[nt][3]));
        }
        tm0 = fmaxf(tm0, __shfl_xor_sync(0xffffffffu, tm0, 1));
        tm0 = fmaxf(tm0, __shfl_xor_sync(0xffffffffu, tm0, 2));
        tm1 = fmaxf(tm1, __shfl_xor_sync(0xffffffffu, tm1, 1));
        tm1 = fmaxf(tm1, __shfl_xor_sync(0xffffffffu, tm1, 2));

        float mn0 = fmaxf(mrow[0], tm0), mn1 = fmaxf(mrow[1], tm1);
        float f0 = __expf(mrow[0] - mn0), f1 = __expf(mrow[1] - mn1);
        mrow[0] = mn0; mrow[1] = mn1;
        lrow[0] *= f0; lrow[1] *= f1;
        #pragma unroll
        for (int nt = 0; nt < 16; nt++) {
            o[nt][0] *= f0; o[nt][1] *= f0;
            o[nt][2] *= f1; o[nt][3] *= f1;
        }

        float ps0 = 0.f, ps1 = 0.f;
        #pragma unroll
        for (int nt = 0; nt < 8; nt++) {
            int col = nt * 8 + 2 * t;
            float p0 = __expf(s[nt][0] - mn0); ps0 += p0;
            float p1 = __expf(s[nt][1] - mn0); ps0 += p1;
            float p2 = __expf(s[nt][2] - mn1); ps1 += p2;
            float p3 = __expf(s[nt][3] - mn1); ps1 += p3;
            Ps[prow0 + col]     = f2tf(p0);
            Ps[prow0 + col + 1] = f2tf(p1);
            Ps[prow1 + col]     = f2tf(p2);
            Ps[prow1 + col + 1] = f2tf(p3);
        }
        ps0 += __shfl_xor_sync(0xffffffffu, ps0, 1);
        ps0 += __shfl_xor_sync(0xffffffffu, ps0, 2);
        ps1 += __shfl_xor_sync(0xffffffffu, ps1, 1);
        ps1 += __shfl_xor_sync(0xffffffffu, ps1, 2);
        lrow[0] += ps0; lrow[1] += ps1;
        __syncwarp();

        // V(kt) ready
        if (kt + 1 < NT) { CP_WAIT(1); } else { CP_WAIT(0); }
        __syncthreads();

        // ---- O(16x128) += P(16x64) @ V(64x128) ----
        #pragma unroll
        for (int ks = 0; ks < 8; ks++) {
            const int kb = ks * 8;
            uint32_t a[4];
            a[0] = Ps[prow0 + kb + t];
            a[1] = Ps[prow1 + kb + t];
            a[2] = Ps[prow0 + kb + t + 4];
            a[3] = Ps[prow1 + kb + t + 4];
            #pragma unroll
            for (int nt = 0; nt < 16; nt++) {
                int cn = nt * 8 + g;
                uint32_t b0 = Vs[(kb + t) * SVm + cn];
                uint32_t b1 = Vs[(kb + t + 4) * SVm + cn];
                mma8(o[nt], a, b0, b1);
            }
        }
        __syncthreads();   // all warps done with V(kt) before overwrite
        if (kt + 1 < NT) { load_V(kt + 1); CP_COMMIT; }
    }

    // epilogue: normalize + pack bf16 hi/lo for the O-projection
    float inv0 = 1.f / lrow[0], inv1 = 1.f / lrow[1];
    const size_t obp = ((size_t)(b * SEQ + qt * 128 + warp * 16 + g)) * HID2 + h * (HD / 2);
    #pragma unroll
    for (int nt = 0; nt < 16; nt++) {
        int cp = nt * 4 + t;   // packed column (pairs 2t,2t+1 within n8)
        float v00 = o[nt][0] * inv0, v01 = o[nt][1] * inv0;
        float v10 = o[nt][2] * inv1, v11 = o[nt][3] * inv1;
        uint32_t h0, l0, h1, l1;
        packsplit_bf(v00, v01, h0, l0);
        packsplit_bf(v10, v11, h1, l1);
        OutH[obp + cp]            = h0;
        OutL[obp + cp]            = l0;
        OutH[obp + 8 * HID2 + cp] = h1;
        OutL[obp + 8 * HID2 + cp] = l1;
    }
}

// ---------------- launch ----------------
extern "C" void kernel_launch(void* const* d_in, const int* in_sizes, int n_in,
                              void* d_out, int out_size)
{
    const float* hidden = (const float*)d_in[0];
    const float* Wq = (const float*)d_in[1];
    const float* bq = (const float*)d_in[2];
    const float* Wk = (const float*)d_in[3];
    const float* bk = (const float*)d_in[4];
    const float* Wv = (const float*)d_in[5];
    const float* bv = (const float*)d_in[6];
    const float* Wo = (const float*)d_in[7];
    const float* bo = (const float*)d_in[8];
    float* out = (float*)d_out;

    uint32_t *Hh, *Hl, *Wqh, *Wql, *Woh, *Wol, *Wkh, *Wkl, *Wvh, *Wvl;
    uint32_t *Qtp, *Ktp, *Vtp, *Ahp, *Alp;
    cudaGetSymbolAddress((void**)&Hh,  g_Hh);  cudaGetSymbolAddress((void**)&Hl,  g_Hl);
    cudaGetSymbolAddress((void**)&Wqh, g_Wqh); cudaGetSymbolAddress((void**)&Wql, g_Wql);
    cudaGetSymbolAddress((void**)&Woh, g_Woh); cudaGetSymbolAddress((void**)&Wol, g_Wol);
    cudaGetSymbolAddress((void**)&Wkh, g_Wkh); cudaGetSymbolAddress((void**)&Wkl, g_Wkl);
    cudaGetSymbolAddress((void**)&Wvh, g_Wvh); cudaGetSymbolAddress((void**)&Wvl, g_Wvl);
    cudaGetSymbolAddress((void**)&Qtp, g_Qt);
    cudaGetSymbolAddress((void**)&Ktp, g_Kt);  cudaGetSymbolAddress((void**)&Vtp, g_Vt);
    cudaGetSymbolAddress((void**)&Ahp, g_Ah);  cudaGetSymbolAddress((void**)&Alp, g_Al);

    cudaFuncSetAttribute(gemm_bf3<0>, cudaFuncAttributeMaxDynamicSharedMemorySize, GEMM_SMEM);
    cudaFuncSetAttribute(gemm_bf3<1>, cudaFuncAttributeMaxDynamicSharedMemorySize, GEMM_SMEM);
    cudaFuncSetAttribute(attn_tf32,   cudaFuncAttributeMaxDynamicSharedMemorySize, ATTN_SMEM);

    const float scale = 0.08838834764831845f;   // 1/sqrt(128)

    // one-time packs
    packA_bf<<<(MTOT*HID2 + 255)/256, 256>>>((const float2*)hidden, Hh, Hl, MTOT*HID2);
    packB_bf<<<(HID2*HID  + 255)/256, 256>>>(Wq, Wqh, Wql, HID, HID2*HID);
    packB_bf<<<(HID2*HD   + 255)/256, 256>>>(Wk, Wkh, Wkl, HD,  HID2*HD);
    packB_bf<<<(HID2*HD   + 255)/256, 256>>>(Wv, Wvh, Wvl, HD,  HID2*HD);
    packB_bf<<<(HID2*HID  + 255)/256, 256>>>(Wo, Woh, Wol, HID, HID2*HID);

    // K / V projections fused (tf32 out), N=128
    {
        dim3 grid(1, MTOT / 128, 2);
        gemm_bf3<1><<<grid, 256, GEMM_SMEM>>>(Hh, Hl,
                                              Wkh, Wkl, bk, Ktp,
                                              Wvh, Wvl, bv, Vtp,
                                              HD, HID, 1.0f);
    }
    // Q projection (tf32 out, scale folded)
    {
        dim3 grid(HID / 128, MTOT / 128, 1);
        gemm_bf3<1><<<grid, 256, GEMM_SMEM>>>(Hh, Hl,
                                              Wqh, Wql, bq, Qtp,
                                              Wqh, Wql, bq, Qtp,
                                              HID, HID, scale);
    }
    // attention
    {
        dim3 grid(SEQ / 128, NH, BATCH);
        attn_tf32<<<grid, 256, ATTN_SMEM>>>(Qtp, Ktp, Vtp, Ahp, Alp);
    }
    // O projection (fp32 out) -> d_out
    {
        dim3 grid(HID / 128, MTOT / 128, 1);
        gemm_bf3<0><<<grid, 256, GEMM_SMEM>>>(Ahp, Alp,
                                              Woh, Wol, bo, out,
                                              Woh, Wol, bo, out,
                                              HID, HID, 1.0f);
    }
}

// round 12
// speedup vs baseline: 4.8584x; 1.4560x over previous
#include <cuda_runtime.h>
#include <cstdint>

#define HID 2048
#define SEQ 2048
#define BATCH 2
#define NH 16
#define HD 128
#define MTOT (BATCH*SEQ)   /* 4096 */
#define HID2 (HID/2)

// ---------------- scratch (no allocations allowed) ----------------
__device__ uint32_t g_Hh[MTOT*HID2],  g_Hl[MTOT*HID2];    // hidden, bf16x2 packed along K
__device__ uint32_t g_Wqh[HID2*HID],  g_Wql[HID2*HID];    // weights, packed along K
__device__ uint32_t g_Woh[HID2*HID],  g_Wol[HID2*HID];
__device__ uint32_t g_Wkh[HID2*HD],   g_Wkl[HID2*HD];
__device__ uint32_t g_Wvh[HID2*HD],   g_Wvl[HID2*HD];
__device__ uint32_t g_Qt[MTOT*HID];                       // Q tf32, scale folded
__device__ uint32_t g_Kt[MTOT*HD],    g_Vt[MTOT*HD];      // K,V tf32
__device__ uint32_t g_Ah[MTOT*HID2],  g_Al[MTOT*HID2];    // attn out, bf16x2 packed

// ---------------- numeric helpers ----------------
__device__ __forceinline__ uint32_t f2tf(float x) {
    uint32_t r; asm("cvt.rna.tf32.f32 %0, %1;" : "=r"(r) : "f"(x)); return r;
}
__device__ __forceinline__ uint16_t f2bf(float x) {
    uint16_t r; asm("cvt.rn.bf16.f32 %0, %1;" : "=h"(r) : "f"(x)); return r;
}
__device__ __forceinline__ float bf2f(uint16_t b) {
    return __uint_as_float(((uint32_t)b) << 16);
}
__device__ __forceinline__ void packsplit_bf(float x0, float x1, uint32_t &hi, uint32_t &lo) {
    uint16_t h0 = f2bf(x0), h1 = f2bf(x1);
    hi = (uint32_t)h0 | ((uint32_t)h1 << 16);
    uint16_t l0 = f2bf(x0 - bf2f(h0)), l1 = f2bf(x1 - bf2f(h1));
    lo = (uint32_t)l0 | ((uint32_t)l1 << 16);
}
__device__ __forceinline__ void mma8(float* d, const uint32_t* a, uint32_t b0, uint32_t b1) {
    asm volatile(
        "mma.sync.aligned.m16n8k8.row.col.f32.tf32.tf32.f32 "
        "{%0,%1,%2,%3}, {%4,%5,%6,%7}, {%8,%9}, {%0,%1,%2,%3};"
        : "+f"(d[0]), "+f"(d[1]), "+f"(d[2]), "+f"(d[3])
        : "r"(a[0]), "r"(a[1]), "r"(a[2]), "r"(a[3]), "r"(b0), "r"(b1));
}
__device__ __forceinline__ void mma16(float* d, const uint32_t* a, uint32_t b0, uint32_t b1) {
    asm volatile(
        "mma.sync.aligned.m16n8k16.row.col.f32.bf16.bf16.f32 "
        "{%0,%1,%2,%3}, {%4,%5,%6,%7}, {%8,%9}, {%0,%1,%2,%3};"
        : "+f"(d[0]), "+f"(d[1]), "+f"(d[2]), "+f"(d[3])
        : "r"(a[0]), "r"(a[1]), "r"(a[2]), "r"(a[3]), "r"(b0), "r"(b1));
}
__device__ __forceinline__ uint32_t s2u(const void* p) {
    return (uint32_t)__cvta_generic_to_shared(p);
}
__device__ __forceinline__ void cp16(uint32_t dst, const void* src) {
    asm volatile("cp.async.cg.shared.global [%0], [%1], 16;" :: "r"(dst), "l"(src));
}
#define CP_COMMIT  asm volatile("cp.async.commit_group;" ::: "memory")
#define CP_WAIT(n) asm volatile("cp.async.wait_group %0;" :: "n"(n) : "memory")

// ---------------- one-time pack (ALL arrays, single launch) ----------------
__global__ void pack_all(
    const float* __restrict__ H,  const float* __restrict__ Wq,
    const float* __restrict__ Wk, const float* __restrict__ Wv,
    const float* __restrict__ Wo,
    uint32_t* __restrict__ Hh,  uint32_t* __restrict__ Hl,
    uint32_t* __restrict__ Wqh, uint32_t* __restrict__ Wql,
    uint32_t* __restrict__ Wkh, uint32_t* __restrict__ Wkl,
    uint32_t* __restrict__ Wvh, uint32_t* __restrict__ Wvl,
    uint32_t* __restrict__ Woh, uint32_t* __restrict__ Wol)
{
    int i = blockIdx.x * 256 + threadIdx.x;
    const int nH = MTOT * HID2, nQ = HID2 * HID, nK = HID2 * HD;
    if (i < nH) {
        float2 v = ((const float2*)H)[i];
        packsplit_bf(v.x, v.y, Hh[i], Hl[i]);
    } else if ((i -= nH) < nQ) {
        int kp = i / HID, n = i - kp * HID;
        packsplit_bf(Wq[(size_t)(2 * kp) * HID + n], Wq[(size_t)(2 * kp + 1) * HID + n],
                     Wqh[i], Wql[i]);
    } else if ((i -= nQ) < nK) {
        int kp = i / HD, n = i - kp * HD;
        packsplit_bf(Wk[(size_t)(2 * kp) * HD + n], Wk[(size_t)(2 * kp + 1) * HD + n],
                     Wkh[i], Wkl[i]);
    } else if ((i -= nK) < nK) {
        int kp = i / HD, n = i - kp * HD;
        packsplit_bf(Wv[(size_t)(2 * kp) * HD + n], Wv[(size_t)(2 * kp + 1) * HD + n],
                     Wvh[i], Wvl[i]);
    } else if ((i -= nK) < nQ) {
        int kp = i / HID, n = i - kp * HID;
        packsplit_bf(Wo[(size_t)(2 * kp) * HID + n], Wo[(size_t)(2 * kp + 1) * HID + n],
                     Woh[i], Wol[i]);
    }
}

// ======================================================================
// bf16x3 GEMM, 512 threads / 16 warps, block tile (128*MT) x 128, BK=32.
// Warp tile (16*MT) x 64. cp.async double-buffered. 1 CTA/SM, no reg cap
// -> 4 warps/SMSP with zero spills (fixes R11's capped-reg occupancy trap).
// TFOUT=0: C float (+bias). TFOUT=1: C uint32 tf32 of (acc+bias)*prescale.
// gridDim.z selects operand set 0/1 (fused K/V projection).
// ======================================================================
#define SA 20     /* A smem stride (u32): 20%32=4 -> frag banks bijective */
#define SB 136    /* B smem stride (u32): 136%32=8 -> frag banks bijective */
#define GEMM_SMEM(MT) ((4*(128*(MT))*SA + 4*16*SB) * 4)
/* MT=2: 116736 B ; MT=1: 75776 B */

template<int MT, int TFOUT>
__global__ __launch_bounds__(512) void gemm_bf3(
    const uint32_t* __restrict__ Ahp, const uint32_t* __restrict__ Alp,
    const uint32_t* __restrict__ Bh0, const uint32_t* __restrict__ Bl0,
    const float* __restrict__ bias0, void* __restrict__ C0,
    const uint32_t* __restrict__ Bh1, const uint32_t* __restrict__ Bl1,
    const float* __restrict__ bias1, void* __restrict__ C1,
    int N, int K, float prescale)
{
    constexpr int BM   = 128 * MT;
    constexpr int ASTG = BM * SA;
    constexpr int BSTG = 16 * SB;

    extern __shared__ uint32_t smg[];
    uint32_t* sAh = smg;                 // 2 x ASTG
    uint32_t* sAl = sAh + 2*ASTG;
    uint32_t* sBh = sAl + 2*ASTG;        // 2 x BSTG
    uint32_t* sBl = sBh + 2*BSTG;
    const uint32_t aAh = s2u(sAh), aAl = s2u(sAl);
    const uint32_t aBh = s2u(sBh), aBl = s2u(sBl);

    const uint32_t* Bh   = blockIdx.z ? Bh1   : Bh0;
    const uint32_t* Bl   = blockIdx.z ? Bl1   : Bl0;
    const float*    bias = blockIdx.z ? bias1 : bias0;
    void*           C    = blockIdx.z ? C1    : C0;

    const int tid  = threadIdx.x;
    const int lane = tid & 31, wid = tid >> 5;
    const int g = lane >> 2, t = lane & 3;
    const int wm = (wid >> 1) * (16 * MT);
    const int wn = (wid & 1) * 64;
    const int row0 = blockIdx.y * BM;
    const int col0 = blockIdx.x * 128;
    const int K2 = K >> 1;

    float acc[MT][8][4];
    #pragma unroll
    for (int i = 0; i < MT; i++)
        #pragma unroll
        for (int j = 0; j < 8; j++)
            #pragma unroll
            for (int c = 0; c < 4; c++) acc[i][j][c] = 0.f;

    auto load_stage = [&](int kp0, int st) {
        // A: BM rows x 16 u32 -> BM*4 float4 chunks per array
        #pragma unroll
        for (int j = 0; j < MT; j++) {
            int idx = tid + j * 512;
            int r = idx >> 2, c = (idx & 3) * 4;
            size_t go = (size_t)(row0 + r) * K2 + kp0 + c;
            uint32_t so = (uint32_t)(st * ASTG + r * SA + c) * 4;
            cp16(aAh + so, Ahp + go);
            cp16(aAl + so, Alp + go);
        }
        // B: 16 rows x 128 u32 -> 512 chunks per array
        {
            int r = tid >> 5, c = (tid & 31) * 4;
            size_t go = (size_t)(kp0 + r) * N + col0 + c;
            uint32_t so = (uint32_t)(st * BSTG + r * SB + c) * 4;
            cp16(aBh + so, Bh + go);
            cp16(aBl + so, Bl + go);
        }
    };

    const int NIT = K / 32;              // 16 packed rows per iter
    load_stage(0, 0); CP_COMMIT;

    for (int it = 0; it < NIT; ++it) {
        const int st = it & 1;
        if (it + 1 < NIT) { load_stage((it + 1) * 16, st ^ 1); CP_COMMIT; CP_WAIT(1); }
        else              { CP_WAIT(0); }
        __syncthreads();

        const uint32_t* Ah_s = sAh + st * ASTG;
        const uint32_t* Al_s = sAl + st * ASTG;
        const uint32_t* Bh_s = sBh + st * BSTG;
        const uint32_t* Bl_s = sBl + st * BSTG;

        #pragma unroll
        for (int s = 0; s < 2; s++) {            // two k16 steps per BK=32
            const int kb = s * 8;                // packed-u32 offset
            uint32_t ah[MT][4], al[MT][4];
            #pragma unroll
            for (int mt = 0; mt < MT; mt++) {
                int rm = wm + mt * 16 + g;
                ah[mt][0] = Ah_s[rm * SA + kb + t];
                ah[mt][1] = Ah_s[(rm + 8) * SA + kb + t];
                ah[mt][2] = Ah_s[rm * SA + kb + t + 4];
                ah[mt][3] = Ah_s[(rm + 8) * SA + kb + t + 4];
                al[mt][0] = Al_s[rm * SA + kb + t];
                al[mt][1] = Al_s[(rm + 8) * SA + kb + t];
                al[mt][2] = Al_s[rm * SA + kb + t + 4];
                al[mt][3] = Al_s[(rm + 8) * SA + kb + t + 4];
            }
            #pragma unroll
            for (int nt = 0; nt < 8; nt++) {
                int cn = wn + nt * 8 + g;
                uint32_t bh0 = Bh_s[(kb + t) * SB + cn];
                uint32_t bh1 = Bh_s[(kb + t + 4) * SB + cn];
                uint32_t bl0 = Bl_s[(kb + t) * SB + cn];
                uint32_t bl1 = Bl_s[(kb + t + 4) * SB + cn];
                #pragma unroll
                for (int mt = 0; mt < MT; mt++) {
                    mma16(acc[mt][nt], ah[mt], bh0, bh1);   // hi*hi
                    mma16(acc[mt][nt], al[mt], bh0, bh1);   // lo*hi
                    mma16(acc[mt][nt], ah[mt], bl0, bl1);   // hi*lo
                }
            }
        }
        __syncthreads();
    }

    #pragma unroll
    for (int mt = 0; mt < MT; mt++) {
        int row = row0 + wm + mt * 16 + g;
        #pragma unroll
        for (int nt = 0; nt < 8; nt++) {
            int col = col0 + wn + nt * 8 + 2 * t;
            float bx = bias[col], by = bias[col + 1];
            float v00 = acc[mt][nt][0] + bx, v01 = acc[mt][nt][1] + by;
            float v10 = acc[mt][nt][2] + bx, v11 = acc[mt][nt][3] + by;
            if (TFOUT) {
                uint32_t* Cu = (uint32_t*)C;
                uint2 a = { f2tf(v00 * prescale), f2tf(v01 * prescale) };
                uint2 b = { f2tf(v10 * prescale), f2tf(v11 * prescale) };
                *(uint2*)(Cu + (size_t)row * N + col)       = a;
                *(uint2*)(Cu + (size_t)(row + 8) * N + col) = b;
            } else {
                float* Cf = (float*)C;
                *(float2*)(Cf + (size_t)row * N + col)       = make_float2(v00, v01);
                *(float2*)(Cf + (size_t)(row + 8) * N + col) = make_float2(v10, v11);
            }
        }
    }
}

// ======================================================================
// Flash attention, tf32 mma (unchanged from R11 — proven, rel_err 3.4e-4).
// Block = (b, h, 128-q-row tile), 256 thr. Warp w owns q rows [16w,16w+16).
// K double-buffered; V single-buffered. Epilogue emits packed-bf16 hi/lo.
// ======================================================================
#define SQm 132
#define SKm 132
#define SVm 136
#define SPm 68
#define ATTN_SMEM ((128*SQm + 2*64*SKm + 64*SVm + 128*SPm) * 4)   /* 204800 B */

__global__ __launch_bounds__(256) void attn_tf32(
    const uint32_t* __restrict__ Qt, const uint32_t* __restrict__ Kt,
    const uint32_t* __restrict__ Vt,
    uint32_t* __restrict__ OutH, uint32_t* __restrict__ OutL)
{
    extern __shared__ uint32_t sm[];
    uint32_t* Qs = sm;                    // 128 x SQm
    uint32_t* Ks = Qs + 128 * SQm;        // 2 x 64 x SKm
    uint32_t* Vs = Ks + 2 * 64 * SKm;     // 64 x SVm
    uint32_t* Ps = Vs + 64 * SVm;         // 128 x SPm
    const uint32_t aQ = s2u(Qs), aK = s2u(Ks), aV = s2u(Vs);

    const int tid  = threadIdx.x;
    const int lane = tid & 31, warp = tid >> 5;
    const int g = lane >> 2, t = lane & 3;
    const int qt = blockIdx.x, h = blockIdx.y, b = blockIdx.z;

    const size_t qbase = ((size_t)(b * SEQ + qt * 128)) * HID + h * HD;
    const size_t kvb   = (size_t)b * SEQ * HD;

    auto load_K = [&](int tile, int st) {
        #pragma unroll
        for (int j = 0; j < 8; j++) {
            int idx = tid + j * 256;
            int r = idx >> 5, c = (idx & 31) * 4;
            cp16(aK + (uint32_t)(st * 64 * SKm + r * SKm + c) * 4,
                 Kt + kvb + (size_t)(tile * 64 + r) * HD + c);
        }
    };
    auto load_V = [&](int tile) {
        #pragma unroll
        for (int j = 0; j < 8; j++) {
            int idx = tid + j * 256;
            int r = idx >> 5, c = (idx & 31) * 4;
            cp16(aV + (uint32_t)(r * SVm + c) * 4,
                 Vt + kvb + (size_t)(tile * 64 + r) * HD + c);
        }
    };

    // prologue: Q + K0 + V0 in one group
    #pragma unroll
    for (int j = 0; j < 16; j++) {
        int idx = tid + j * 256;
        int r = idx >> 5, c = (idx & 31) * 4;
        cp16(aQ + (uint32_t)(r * SQm + c) * 4, Qt + qbase + (size_t)r * HID + c);
    }
    load_K(0, 0);
    load_V(0);
    CP_COMMIT;

    float mrow[2] = { -1e30f, -1e30f };
    float lrow[2] = { 0.f, 0.f };
    float o[16][4];
    #pragma unroll
    for (int nt = 0; nt < 16; nt++)
        #pragma unroll
        for (int c = 0; c < 4; c++) o[nt][c] = 0.f;

    const int prow0 = (warp * 16 + g) * SPm;
    const int prow1 = prow0 + 8 * SPm;
    const int NT = SEQ / 64;

    for (int kt = 0; kt < NT; kt++) {
        if (kt == 0) { CP_WAIT(0); } else { CP_WAIT(1); }   // K(kt) ready
        __syncthreads();

        // ---- S(16x64) = Q_warp @ K^T ----
        const uint32_t* Kst = Ks + (kt & 1) * 64 * SKm;
        float s[8][4];
        #pragma unroll
        for (int nt = 0; nt < 8; nt++)
            #pragma unroll
            for (int c = 0; c < 4; c++) s[nt][c] = 0.f;

        #pragma unroll
        for (int ks = 0; ks < 16; ks++) {
            const int kb = ks * 8;
            const int rm = warp * 16 + g;
            uint32_t a[4];
            a[0] = Qs[rm * SQm + kb + t];
            a[1] = Qs[(rm + 8) * SQm + kb + t];
            a[2] = Qs[rm * SQm + kb + t + 4];
            a[3] = Qs[(rm + 8) * SQm + kb + t + 4];
            #pragma unroll
            for (int nt = 0; nt < 8; nt++) {
                int cn = nt * 8 + g;
                uint32_t b0 = Kst[cn * SKm + kb + t];
                uint32_t b1 = Kst[cn * SKm + kb + t + 4];
                mma8(s[nt], a, b0, b1);
            }
        }

        // prefetch K(kt+1) (overlaps softmax + PV)
        if (kt + 1 < NT) { load_K(kt + 1, (kt + 1) & 1); CP_COMMIT; }

        // ---- online softmax ----
        float tm0 = -1e30f, tm1 = -1e30f;
        #pragma unroll
        for (int nt = 0; nt < 8; nt++) {
            tm0 = fmaxf(tm0, fmaxf(s[nt][0], s[nt][1]));
            tm1 = fmaxf(tm1, fmaxf(s[nt][2], s[nt][3]));
        }
        tm0 = fmaxf(tm0, __shfl_xor_sync(0xffffffffu, tm0, 1));
        tm0 = fmaxf(tm0, __shfl_xor_sync(0xffffffffu, tm0, 2));
        tm1 = fmaxf(tm1, __shfl_xor_sync(0xffffffffu, tm1, 1));
        tm1 = fmaxf(tm1, __shfl_xor_sync(0xffffffffu, tm1, 2));

        float mn0 = fmaxf(mrow[0], tm0), mn1 = fmaxf(mrow[1], tm1);
        float f0 = __expf(mrow[0] - mn0), f1 = __expf(mrow[1] - mn1);
        mrow[0] = mn0; mrow[1] = mn1;
        lrow[0] *= f0; lrow[1] *= f1;
        #pragma unroll
        for (int nt = 0; nt < 16; nt++) {
            o[nt][0] *= f0; o[nt][1] *= f0;
            o[nt][2] *= f1; o[nt][3] *= f1;
        }

        float ps0 = 0.f, ps1 = 0.f;
        #pragma unroll
        for (int nt = 0; nt < 8; nt++) {
            int col = nt * 8 + 2 * t;
            float p0 = __expf(s[nt][0] - mn0); ps0 += p0;
            float p1 = __expf(s[nt][1] - mn0); ps0 += p1;
            float p2 = __expf(s[nt][2] - mn1); ps1 += p2;
            float p3 = __expf(s[nt][3] - mn1); ps1 += p3;
            Ps[prow0 + col]     = f2tf(p0);
            Ps[prow0 + col + 1] = f2tf(p1);
            Ps[prow1 + col]     = f2tf(p2);
            Ps[prow1 + col + 1] = f2tf(p3);
        }
        ps0 += __shfl_xor_sync(0xffffffffu, ps0, 1);
        ps0 += __shfl_xor_sync(0xffffffffu, ps0, 2);
        ps1 += __shfl_xor_sync(0xffffffffu, ps1, 1);
        ps1 += __shfl_xor_sync(0xffffffffu, ps1, 2);
        lrow[0] += ps0; lrow[1] += ps1;
        __syncwarp();

        // V(kt) ready
        if (kt + 1 < NT) { CP_WAIT(1); } else { CP_WAIT(0); }
        __syncthreads();

        // ---- O(16x128) += P(16x64) @ V(64x128) ----
        #pragma unroll
        for (int ks = 0; ks < 8; ks++) {
            const int kb = ks * 8;
            uint32_t a[4];
            a[0] = Ps[prow0 + kb + t];
            a[1] = Ps[prow1 + kb + t];
            a[2] = Ps[prow0 + kb + t + 4];
            a[3] = Ps[prow1 + kb + t + 4];
            #pragma unroll
            for (int nt = 0; nt < 16; nt++) {
                int cn = nt * 8 + g;
                uint32_t b0 = Vs[(kb + t) * SVm + cn];
                uint32_t b1 = Vs[(kb + t + 4) * SVm + cn];
                mma8(o[nt], a, b0, b1);
            }
        }
        __syncthreads();   // all warps done with V(kt) before overwrite
        if (kt + 1 < NT) { load_V(kt + 1); CP_COMMIT; }
    }

    // epilogue: normalize + pack bf16 hi/lo for the O-projection
    float inv0 = 1.f / lrow[0], inv1 = 1.f / lrow[1];
    const size_t obp = ((size_t)(b * SEQ + qt * 128 + warp * 16 + g)) * HID2 + h * (HD / 2);
    #pragma unroll
    for (int nt = 0; nt < 16; nt++) {
        int cp = nt * 4 + t;   // packed column (pairs 2t,2t+1 within n8)
        float v00 = o[nt][0] * inv0, v01 = o[nt][1] * inv0;
        float v10 = o[nt][2] * inv1, v11 = o[nt][3] * inv1;
        uint32_t h0, l0, h1, l1;
        packsplit_bf(v00, v01, h0, l0);
        packsplit_bf(v10, v11, h1, l1);
        OutH[obp + cp]            = h0;
        OutL[obp + cp]            = l0;
        OutH[obp + 8 * HID2 + cp] = h1;
        OutL[obp + 8 * HID2 + cp] = l1;
    }
}

// ---------------- launch ----------------
extern "C" void kernel_launch(void* const* d_in, const int* in_sizes, int n_in,
                              void* d_out, int out_size)
{
    const float* hidden = (const float*)d_in[0];
    const float* Wq = (const float*)d_in[1];
    const float* bq = (const float*)d_in[2];
    const float* Wk = (const float*)d_in[3];
    const float* bk = (const float*)d_in[4];
    const float* Wv = (const float*)d_in[5];
    const float* bv = (const float*)d_in[6];
    const float* Wo = (const float*)d_in[7];
    const float* bo = (const float*)d_in[8];
    float* out = (float*)d_out;

    uint32_t *Hh, *Hl, *Wqh, *Wql, *Woh, *Wol, *Wkh, *Wkl, *Wvh, *Wvl;
    uint32_t *Qtp, *Ktp, *Vtp, *Ahp, *Alp;
    cudaGetSymbolAddress((void**)&Hh,  g_Hh);  cudaGetSymbolAddress((void**)&Hl,  g_Hl);
    cudaGetSymbolAddress((void**)&Wqh, g_Wqh); cudaGetSymbolAddress((void**)&Wql, g_Wql);
    cudaGetSymbolAddress((void**)&Woh, g_Woh); cudaGetSymbolAddress((void**)&Wol, g_Wol);
    cudaGetSymbolAddress((void**)&Wkh, g_Wkh); cudaGetSymbolAddress((void**)&Wkl, g_Wkl);
    cudaGetSymbolAddress((void**)&Wvh, g_Wvh); cudaGetSymbolAddress((void**)&Wvl, g_Wvl);
    cudaGetSymbolAddress((void**)&Qtp, g_Qt);
    cudaGetSymbolAddress((void**)&Ktp, g_Kt);  cudaGetSymbolAddress((void**)&Vtp, g_Vt);
    cudaGetSymbolAddress((void**)&Ahp, g_Ah);  cudaGetSymbolAddress((void**)&Alp, g_Al);

    cudaFuncSetAttribute(gemm_bf3<1,1>, cudaFuncAttributeMaxDynamicSharedMemorySize, GEMM_SMEM(1));
    cudaFuncSetAttribute(gemm_bf3<2,1>, cudaFuncAttributeMaxDynamicSharedMemorySize, GEMM_SMEM(2));
    cudaFuncSetAttribute(gemm_bf3<2,0>, cudaFuncAttributeMaxDynamicSharedMemorySize, GEMM_SMEM(2));
    cudaFuncSetAttribute(attn_tf32,     cudaFuncAttributeMaxDynamicSharedMemorySize, ATTN_SMEM);

    const float scale = 0.08838834764831845f;   // 1/sqrt(128)

    // one-time packs (single launch)
    {
        int total = MTOT*HID2 + 2*(HID2*HID) + 2*(HID2*HD);
        pack_all<<<(total + 255)/256, 256>>>(hidden, Wq, Wk, Wv, Wo,
                                             Hh, Hl, Wqh, Wql, Wkh, Wkl, Wvh, Wvl, Woh, Wol);
    }
    // K / V projections fused (tf32 out), N=128, BM=128
    {
        dim3 grid(1, MTOT / 128, 2);
        gemm_bf3<1,1><<<grid, 512, GEMM_SMEM(1)>>>(Hh, Hl,
                                                   Wkh, Wkl, bk, Ktp,
                                                   Wvh, Wvl, bv, Vtp,
                                                   HD, HID, 1.0f);
    }
    // Q projection (tf32 out, scale folded), BM=256
    {
        dim3 grid(HID / 128, MTOT / 256, 1);
        gemm_bf3<2,1><<<grid, 512, GEMM_SMEM(2)>>>(Hh, Hl,
                                                   Wqh, Wql, bq, Qtp,
                                                   Wqh, Wql, bq, Qtp,
                                                   HID, HID, scale);
    }
    // attention
    {
        dim3 grid(SEQ / 128, NH, BATCH);
        attn_tf32<<<grid, 256, ATTN_SMEM>>>(Qtp, Ktp, Vtp, Ahp, Alp);
    }
    // O projection (fp32 out) -> d_out, BM=256
    {
        dim3 grid(HID / 128, MTOT / 256, 1);
        gemm_bf3<2,0><<<grid, 512, GEMM_SMEM(2)>>>(Ahp, Alp,
                                                   Woh, Wol, bo, out,
                                                   Woh, Wol, bo, out,
                                                   HID, HID, 1.0f);
    }
}